// round 14
// baseline (speedup 1.0000x reference)
#include <cuda_runtime.h>
#include <cuda_fp16.h>
#include <math.h>
#include <stdint.h>

#define TOKENS 2048
#define HID    1024
#define NEXP   64
#define INTER  512
#define TOPK   8
#define NGRP   8
#define TOPKG  4

#define ROWB    144
#define STG     18432
#define NSTAGE  3
#define SA_OFF  1024
#define SB_OFF  (SA_OFF + NSTAGE * STG)
#define SM_TOT  (SB_OFF + NSTAGE * STG)   // 111616
#define MAXMT   4
#define KSPLIT  8
#define NCHUNK  4
#define ECHUNK  (NEXP / NCHUNK)           // 16 experts per chunk

// ---------------- scratch ----------------------------------------------------
__device__ float  g_logits[TOKENS * NEXP];
__device__ int    g_cnt[NEXP];
__device__ int    g_tok[NEXP * TOKENS];
__device__ float  g_wt[NEXP * TOKENS];
__device__ __half g_h[(size_t)NEXP * TOKENS * INTER];
__device__ __half g_w13h[(size_t)NEXP * 2 * INTER * HID];
__device__ __half g_w2h[(size_t)NEXP * HID * INTER];
__device__ __half g_xh[TOKENS * HID];

// ---------------- helpers ----------------------------------------------------
__device__ __forceinline__ uint32_t smem_u32(const void* p) {
    uint32_t a;
    asm("{ .reg .u64 t; cvta.to.shared.u64 t, %1; cvt.u32.u64 %0, t; }" : "=r"(a) : "l"(p));
    return a;
}
__device__ __forceinline__ uint32_t packh2(float a, float b) {
    __half2 h = __float22half2_rn(make_float2(a, b));
    return *(uint32_t*)&h;
}
__device__ __forceinline__ void cpa16(uint32_t dst, const void* src, uint32_t nbytes) {
    asm volatile("cp.async.cg.shared.global [%0], [%1], 16, %2;"
                 :: "r"(dst), "l"(src), "r"(nbytes) : "memory");
}
#define CP_COMMIT() asm volatile("cp.async.commit_group;" ::: "memory")
#define CP_WAIT1()  asm volatile("cp.async.wait_group 1;" ::: "memory")
__device__ __forceinline__ void ldsm_x4(uint32_t r[4], uint32_t addr) {
    asm volatile("ldmatrix.sync.aligned.m8n8.x4.shared.b16 {%0,%1,%2,%3}, [%4];"
                 : "=r"(r[0]), "=r"(r[1]), "=r"(r[2]), "=r"(r[3]) : "r"(addr));
}
__device__ __forceinline__ void mma_f16(float c[4], const uint32_t a[4],
                                        uint32_t b0, uint32_t b1) {
    asm volatile(
        "mma.sync.aligned.m16n8k16.row.col.f32.f16.f16.f32 "
        "{%0,%1,%2,%3},{%4,%5,%6,%7},{%8,%9},{%0,%1,%2,%3};"
        : "+f"(c[0]), "+f"(c[1]), "+f"(c[2]), "+f"(c[3])
        : "r"(a[0]), "r"(a[1]), "r"(a[2]), "r"(a[3]), "r"(b0), "r"(b1));
}
__device__ __forceinline__ float silu(float g) { return g / (1.f + expf(-g)); }
__device__ __forceinline__ void red_add_v2(float* p, float a, float b) {
    asm volatile("red.global.add.v2.f32 [%0], {%1,%2};" :: "l"(p), "f"(a), "f"(b) : "memory");
}
__device__ __forceinline__ void red_add_v4(float* p, float a, float b, float c, float d) {
    asm volatile("red.global.add.v4.f32 [%0], {%1,%2,%3,%4};"
                 :: "l"(p), "f"(a), "f"(b), "f"(c), "f"(d) : "memory");
}

// ---------------- fp32 -> fp16 streaming conversion (MLP=8) ------------------
__global__ __launch_bounds__(256) void conv_kernel(const float4* __restrict__ src,
                                                   uint4* __restrict__ dst, int n4) {
    int base = blockIdx.x * 1024 + threadIdx.x;
    float4 a[8];
#pragma unroll
    for (int p = 0; p < 4; p++) {
        int idx = base + p * 256;
        a[2 * p]     = __ldg(&src[2 * idx]);
        a[2 * p + 1] = __ldg(&src[2 * idx + 1]);
    }
#pragma unroll
    for (int p = 0; p < 4; p++) {
        int idx = base + p * 256;
        uint4 o;
        o.x = packh2(a[2 * p].x,     a[2 * p].y);
        o.y = packh2(a[2 * p].z,     a[2 * p].w);
        o.z = packh2(a[2 * p + 1].x, a[2 * p + 1].y);
        o.w = packh2(a[2 * p + 1].z, a[2 * p + 1].w);
        dst[idx] = o;
    }
}

// ---------------- router: k-split logits GEMM, red.add partials --------------
__global__ __launch_bounds__(256) void router_kernel(const float* __restrict__ x,
                                                     const float* __restrict__ gw) {
    __shared__ float Xs[16][68];
    __shared__ float Gs[16][68];
    const int m0    = blockIdx.x * 64;
    const int kbase = blockIdx.y * (HID / KSPLIT);
    const int tid   = threadIdx.x;
    const int ty    = tid >> 4;
    const int tx    = tid & 15;

    if (blockIdx.x == 0 && blockIdx.y == 0 && tid < NEXP) g_cnt[tid] = 0;

    float acc[4][4];
#pragma unroll
    for (int i = 0; i < 4; i++)
#pragma unroll
        for (int j = 0; j < 4; j++) acc[i][j] = 0.f;

    const int lrow = tid >> 2;
    const int lk   = (tid & 3) * 4;
    const float* xp = x + (size_t)(m0 + lrow) * HID + kbase + lk;
    const float* gp = gw + (size_t)lrow * HID + kbase + lk;

#pragma unroll
    for (int k0 = 0; k0 < HID / KSPLIT; k0 += 16) {
        float4 xv = *(const float4*)(xp + k0);
        float4 gv = *(const float4*)(gp + k0);
        Xs[lk + 0][lrow] = xv.x; Xs[lk + 1][lrow] = xv.y;
        Xs[lk + 2][lrow] = xv.z; Xs[lk + 3][lrow] = xv.w;
        Gs[lk + 0][lrow] = gv.x; Gs[lk + 1][lrow] = gv.y;
        Gs[lk + 2][lrow] = gv.z; Gs[lk + 3][lrow] = gv.w;
        __syncthreads();
#pragma unroll
        for (int k = 0; k < 16; k++) {
            float4 a = *(const float4*)&Xs[k][ty * 4];
            float4 b = *(const float4*)&Gs[k][tx * 4];
            acc[0][0] += a.x * b.x; acc[0][1] += a.x * b.y; acc[0][2] += a.x * b.z; acc[0][3] += a.x * b.w;
            acc[1][0] += a.y * b.x; acc[1][1] += a.y * b.y; acc[1][2] += a.y * b.z; acc[1][3] += a.y * b.w;
            acc[2][0] += a.z * b.x; acc[2][1] += a.z * b.y; acc[2][2] += a.z * b.z; acc[2][3] += a.z * b.w;
            acc[3][0] += a.w * b.x; acc[3][1] += a.w * b.y; acc[3][2] += a.w * b.z; acc[3][3] += a.w * b.w;
        }
        __syncthreads();
    }

#pragma unroll
    for (int i = 0; i < 4; i++) {
        float* dst = g_logits + (size_t)(m0 + ty * 4 + i) * NEXP + tx * 4;
        red_add_v4(dst, acc[i][0], acc[i][1], acc[i][2], acc[i][3]);
    }
}

// ---------------- grouped top-k routing (exact; sigmoid applied here) --------
__global__ void topk_kernel(const float* __restrict__ bias) {
    int t = blockIdx.x * blockDim.x + threadIdx.x;
    if (t >= TOKENS) return;

    float sraw[NEXP], sb[NEXP];
    const float* lg = g_logits + (size_t)t * NEXP;
#pragma unroll
    for (int e = 0; e < NEXP; e++) {
        sraw[e] = 1.f / (1.f + expf(-lg[e]));
        sb[e]   = sraw[e] + bias[e];
    }

    float gs[NGRP];
#pragma unroll
    for (int g = 0; g < NGRP; g++) {
        float m1 = -1e30f, m2 = -1e30f;
#pragma unroll
        for (int j = 0; j < NEXP / NGRP; j++) {
            float v = sb[g * (NEXP / NGRP) + j];
            if (v > m1) { m2 = m1; m1 = v; } else if (v > m2) { m2 = v; }
        }
        gs[g] = m1 + m2;
    }

    unsigned gsel = 0;
    for (int it = 0; it < TOPKG; it++) {
        int best = -1; float bv = -1e30f;
#pragma unroll
        for (int g = 0; g < NGRP; g++)
            if (!((gsel >> g) & 1u) && gs[g] > bv) { bv = gs[g]; best = g; }
        gsel |= 1u << best;
    }

    unsigned long long esel = 0ull;
    int   ids[TOPK];
    float w[TOPK];
    float wsum = 0.f;
    for (int it = 0; it < TOPK; it++) {
        int best = -1; float bv = -1e30f;
#pragma unroll
        for (int e = 0; e < NEXP; e++) {
            if (((gsel >> (e >> 3)) & 1u) && !((esel >> e) & 1ull)) {
                float v = sb[e];
                if (v > bv) { bv = v; best = e; }
            }
        }
        esel |= 1ull << best;
        ids[it] = best;
        w[it]   = sraw[best];
        wsum   += sraw[best];
    }
    float inv = 1.f / wsum;

    for (int it = 0; it < TOPK; it++) {
        int e   = ids[it];
        int pos = atomicAdd(&g_cnt[e], 1);
        g_tok[e * TOKENS + pos] = t;
        g_wt[e * TOKENS + pos]  = w[it] * inv;
    }
}

// ---------------- expert GEMM1 (fp16, BK=64, 3-stage, frag-pipelined) --------
__global__ __launch_bounds__(256, 2) void w13_k(int e0) {
    extern __shared__ char smem[];
    int* stok = (int*)smem;

    const int e   = e0 + blockIdx.z;
    const int cnt = g_cnt[e];
    const int m0  = blockIdx.y * 128;
    if (m0 >= cnt) return;
    const int n0  = blockIdx.x * 64;

    const int tid = threadIdx.x, lane = tid & 31, wid = tid >> 5;
    const int wm = wid & 1, wn = wid >> 1, t4 = lane & 3, g8 = lane >> 2;

    if (tid < 128) stok[tid] = (m0 + tid < cnt) ? g_tok[e * TOKENS + m0 + tid] : -1;
    __syncthreads();

    const uint32_t sbase = smem_u32(smem);

    const __half* asrc[4]; uint32_t asz[4], aoff[4];
    const __half* bsrc[4];
    const __half* w13e = g_w13h + (size_t)e * (2 * INTER) * HID;
#pragma unroll
    for (int p = 0; p < 4; p++) {
        int q   = tid + p * 256;
        int row = q >> 3, c = q & 7;
        int tk  = stok[row];
        asrc[p] = g_xh + (size_t)(tk >= 0 ? tk : 0) * HID + c * 8;
        asz[p]  = (tk >= 0) ? 16u : 0u;
        aoff[p] = row * ROWB + c * 16;
        int bw  = (row < 64) ? (n0 + row) : (INTER + n0 + (row - 64));
        bsrc[p] = w13e + (size_t)bw * HID + c * 8;
    }
    auto load_stage = [&](int s, int k0) {
#pragma unroll
        for (int p = 0; p < 4; p++) {
            cpa16(sbase + SA_OFF + s * STG + aoff[p], asrc[p] + k0, asz[p]);
            cpa16(sbase + SB_OFF + s * STG + aoff[p], bsrc[p] + k0, 16u);
        }
    };

    const int lr  = ((lane >> 3) & 1) * 8 + (lane & 7);
    const int lkb = (lane >> 4) * 16;
    const uint32_t aAddr = sbase + SA_OFF + (wm * 64 + lr) * ROWB + lkb;
    const uint32_t bAddr = sbase + SB_OFF + (wn * 16 + lr) * ROWB + lkb;

    float acc[4][4][4];
#pragma unroll
    for (int i = 0; i < 4; i++)
#pragma unroll
        for (int j = 0; j < 4; j++)
#pragma unroll
            for (int c = 0; c < 4; c++) acc[i][j][c] = 0.f;

    load_stage(0, 0);  CP_COMMIT();
    load_stage(1, 64); CP_COMMIT();

    uint32_t a[2][4][4], bg[2][4], bu[2][4];

    const int NIT = HID / 64;
    int s = 0, sl = 2;
    for (int it = 0; it < NIT; it++) {
        CP_WAIT1();
        __syncthreads();
        if (it + 2 < NIT) load_stage(sl, (it + 2) * 64);
        CP_COMMIT();

        const uint32_t sOff = s * STG;
#pragma unroll
        for (int mf = 0; mf < 4; mf++)
            ldsm_x4(a[0][mf], aAddr + sOff + mf * 16 * ROWB);
        ldsm_x4(bg[0], bAddr + sOff);
        ldsm_x4(bu[0], bAddr + sOff + 64 * ROWB);

#pragma unroll
        for (int ks = 0; ks < 4; ks++) {
            const int cur = ks & 1, nxt = cur ^ 1;
            if (ks < 3) {
#pragma unroll
                for (int mf = 0; mf < 4; mf++)
                    ldsm_x4(a[nxt][mf], aAddr + sOff + mf * 16 * ROWB + (ks + 1) * 32);
                ldsm_x4(bg[nxt], bAddr + sOff + (ks + 1) * 32);
                ldsm_x4(bu[nxt], bAddr + sOff + 64 * ROWB + (ks + 1) * 32);
            }
#pragma unroll
            for (int mf = 0; mf < 4; mf++) {
                mma_f16(acc[mf][0], a[cur][mf], bg[cur][0], bg[cur][2]);
                mma_f16(acc[mf][1], a[cur][mf], bg[cur][1], bg[cur][3]);
                mma_f16(acc[mf][2], a[cur][mf], bu[cur][0], bu[cur][2]);
                mma_f16(acc[mf][3], a[cur][mf], bu[cur][1], bu[cur][3]);
            }
        }
        if (++s == NSTAGE) s = 0;
        if (++sl == NSTAGE) sl = 0;
    }

#pragma unroll
    for (int mf = 0; mf < 4; mf++) {
        int r0 = wm * 64 + mf * 16 + g8;
        int r1 = r0 + 8;
#pragma unroll
        for (int nf = 0; nf < 2; nf++) {
            int c = n0 + wn * 16 + nf * 8 + t4 * 2;
            if (m0 + r0 < cnt) {
                uint32_t o = packh2(silu(acc[mf][nf][0]) * acc[mf][nf + 2][0],
                                    silu(acc[mf][nf][1]) * acc[mf][nf + 2][1]);
                *(uint32_t*)&g_h[((size_t)e * TOKENS + m0 + r0) * INTER + c] = o;
            }
            if (m0 + r1 < cnt) {
                uint32_t o = packh2(silu(acc[mf][nf][2]) * acc[mf][nf + 2][2],
                                    silu(acc[mf][nf][3]) * acc[mf][nf + 2][3]);
                *(uint32_t*)&g_h[((size_t)e * TOKENS + m0 + r1) * INTER + c] = o;
            }
        }
    }
}

// ---------------- expert GEMM2 (fp16, BK=64, 3-stage, frag-pipelined) --------
__global__ __launch_bounds__(256, 2) void w2_k(float* __restrict__ y, int e0) {
    extern __shared__ char smem[];
    int*   stok = (int*)smem;
    float* swt  = (float*)(smem + 512);

    const int e   = e0 + blockIdx.z;
    const int cnt = g_cnt[e];
    const int m0  = blockIdx.y * 128;
    if (m0 >= cnt) return;
    const int n0  = blockIdx.x * 128;

    const int tid = threadIdx.x, lane = tid & 31, wid = tid >> 5;
    const int wm = wid & 1, wn = wid >> 1, t4 = lane & 3, g8 = lane >> 2;

    if (tid < 128) {
        bool v = m0 + tid < cnt;
        stok[tid] = v ? g_tok[e * TOKENS + m0 + tid] : 0;
        swt[tid]  = v ? g_wt[e * TOKENS + m0 + tid] : 0.f;
    }
    __syncthreads();

    const uint32_t sbase = smem_u32(smem);

    const __half* asrc[4]; uint32_t asz[4], aoff[4];
    const __half* bsrc[4];
    const __half* w2e = g_w2h + (size_t)e * HID * INTER;
#pragma unroll
    for (int p = 0; p < 4; p++) {
        int q   = tid + p * 256;
        int row = q >> 3, c = q & 7;
        bool v  = (m0 + row) < cnt;
        asrc[p] = g_h + ((size_t)e * TOKENS + m0 + row) * INTER + c * 8;
        asz[p]  = v ? 16u : 0u;
        aoff[p] = row * ROWB + c * 16;
        bsrc[p] = w2e + (size_t)(n0 + row) * INTER + c * 8;
    }
    auto load_stage = [&](int s, int k0) {
#pragma unroll
        for (int p = 0; p < 4; p++) {
            cpa16(sbase + SA_OFF + s * STG + aoff[p], asrc[p] + k0, asz[p]);
            cpa16(sbase + SB_OFF + s * STG + aoff[p], bsrc[p] + k0, 16u);
        }
    };

    const int lr  = ((lane >> 3) & 1) * 8 + (lane & 7);
    const int lkb = (lane >> 4) * 16;
    const uint32_t aAddr = sbase + SA_OFF + (wm * 64 + lr) * ROWB + lkb;
    const uint32_t bAddr = sbase + SB_OFF + (wn * 32 + lr) * ROWB + lkb;

    float acc[4][4][4];
#pragma unroll
    for (int i = 0; i < 4; i++)
#pragma unroll
        for (int j = 0; j < 4; j++)
#pragma unroll
            for (int c = 0; c < 4; c++) acc[i][j][c] = 0.f;

    load_stage(0, 0);  CP_COMMIT();
    load_stage(1, 64); CP_COMMIT();

    uint32_t a[2][4][4], b0[2][4], b1[2][4];

    const int NIT = INTER / 64;
    int s = 0, sl = 2;
    for (int it = 0; it < NIT; it++) {
        CP_WAIT1();
        __syncthreads();
        if (it + 2 < NIT) load_stage(sl, (it + 2) * 64);
        CP_COMMIT();

        const uint32_t sOff = s * STG;
#pragma unroll
        for (int mf = 0; mf < 4; mf++)
            ldsm_x4(a[0][mf], aAddr + sOff + mf * 16 * ROWB);
        ldsm_x4(b0[0], bAddr + sOff);
        ldsm_x4(b1[0], bAddr + sOff + 16 * ROWB);

#pragma unroll
        for (int ks = 0; ks < 4; ks++) {
            const int cur = ks & 1, nxt = cur ^ 1;
            if (ks < 3) {
#pragma unroll
                for (int mf = 0; mf < 4; mf++)
                    ldsm_x4(a[nxt][mf], aAddr + sOff + mf * 16 * ROWB + (ks + 1) * 32);
                ldsm_x4(b0[nxt], bAddr + sOff + (ks + 1) * 32);
                ldsm_x4(b1[nxt], bAddr + sOff + 16 * ROWB + (ks + 1) * 32);
            }
#pragma unroll
            for (int mf = 0; mf < 4; mf++) {
                mma_f16(acc[mf][0], a[cur][mf], b0[cur][0], b0[cur][2]);
                mma_f16(acc[mf][1], a[cur][mf], b0[cur][1], b0[cur][3]);
                mma_f16(acc[mf][2], a[cur][mf], b1[cur][0], b1[cur][2]);
                mma_f16(acc[mf][3], a[cur][mf], b1[cur][1], b1[cur][3]);
            }
        }
        if (++s == NSTAGE) s = 0;
        if (++sl == NSTAGE) sl = 0;
    }

#pragma unroll
    for (int mf = 0; mf < 4; mf++) {
        int r0 = wm * 64 + mf * 16 + g8;
        int r1 = r0 + 8;
        bool v0 = (m0 + r0) < cnt;
        bool v1 = (m0 + r1) < cnt;
        int   tok0 = stok[r0], tok1 = stok[r1];
        float wt0 = swt[r0],  wt1 = swt[r1];
#pragma unroll
        for (int nf = 0; nf < 4; nf++) {
            int c = n0 + wn * 32 + nf * 8 + t4 * 2;
            if (v0) red_add_v2(&y[(size_t)tok0 * HID + c],
                               wt0 * acc[mf][nf][0], wt0 * acc[mf][nf][1]);
            if (v1) red_add_v2(&y[(size_t)tok1 * HID + c],
                               wt1 * acc[mf][nf][2], wt1 * acc[mf][nf][3]);
        }
    }
}

// ---------------- launch ------------------------------------------------------
extern "C" void kernel_launch(void* const* d_in, const int* in_sizes, int n_in,
                              void* d_out, int out_size) {
    const float* x    = (const float*)d_in[0];
    const float* gw   = (const float*)d_in[1];
    const float* bias = (const float*)d_in[2];
    const float* w13  = (const float*)d_in[3];
    const float* w2   = (const float*)d_in[4];
    float* y = (float*)d_out;

    cudaFuncSetAttribute(w13_k, cudaFuncAttributeMaxDynamicSharedMemorySize, SM_TOT);
    cudaFuncSetAttribute(w2_k,  cudaFuncAttributeMaxDynamicSharedMemorySize, SM_TOT);

    __half *d_w13h, *d_w2h, *d_xh;
    float  *d_logits;
    cudaGetSymbolAddress((void**)&d_w13h,  g_w13h);
    cudaGetSymbolAddress((void**)&d_w2h,   g_w2h);
    cudaGetSymbolAddress((void**)&d_xh,    g_xh);
    cudaGetSymbolAddress((void**)&d_logits, g_logits);

    // streams + events (created once; capture-safe fork/join pattern)
    static cudaStream_t sc = nullptr, sr = nullptr;
    static cudaEvent_t evRoot = nullptr, evRoute = nullptr;
    static cudaEvent_t evW13c[NCHUNK], evW2c[NCHUNK];
    if (!sc) {
        cudaStreamCreateWithFlags(&sc, cudaStreamNonBlocking);
        cudaStreamCreateWithFlags(&sr, cudaStreamNonBlocking);
        cudaEventCreateWithFlags(&evRoot,  cudaEventDisableTiming);
        cudaEventCreateWithFlags(&evRoute, cudaEventDisableTiming);
        for (int c = 0; c < NCHUNK; c++) {
            cudaEventCreateWithFlags(&evW13c[c], cudaEventDisableTiming);
            cudaEventCreateWithFlags(&evW2c[c],  cudaEventDisableTiming);
        }
    }

    cudaEventRecord(evRoot, 0);

    // ---- sr: logits memset + router + topk ----
    cudaStreamWaitEvent(sr, evRoot, 0);
    cudaMemsetAsync(d_logits, 0, (size_t)TOKENS * NEXP * sizeof(float), sr);
    router_kernel<<<dim3(TOKENS / 64, KSPLIT), 256, 0, sr>>>(x, gw);
    topk_kernel<<<TOKENS / 64, 64, 0, sr>>>(bias);
    cudaEventRecord(evRoute, sr);

    // ---- sc: conv x, then w13 chunks, then y memset + w2 chunks ----
    cudaStreamWaitEvent(sc, evRoot, 0);
    {
        int n4 = TOKENS * HID / 8;
        conv_kernel<<<n4 / 1024, 256, 0, sc>>>((const float4*)x, (uint4*)d_xh, n4);

        const size_t w13ChunkElems = (size_t)ECHUNK * 2 * INTER * HID;
        int n4c = (int)(w13ChunkElems / 8);
        for (int c = 0; c < NCHUNK; c++) {
            conv_kernel<<<n4c / 1024, 256, 0, sc>>>(
                (const float4*)(w13 + c * w13ChunkElems),
                (uint4*)(d_w13h + c * w13ChunkElems), n4c);
            cudaEventRecord(evW13c[c], sc);
        }

        cudaMemsetAsync(y, 0, (size_t)TOKENS * HID * sizeof(float), sc);
        const size_t w2ChunkElems = (size_t)ECHUNK * HID * INTER;
        n4c = (int)(w2ChunkElems / 8);
        for (int c = 0; c < NCHUNK; c++) {
            conv_kernel<<<n4c / 1024, 256, 0, sc>>>(
                (const float4*)(w2 + c * w2ChunkElems),
                (uint4*)(d_w2h + c * w2ChunkElems), n4c);
            cudaEventRecord(evW2c[c], sc);
        }
    }

    // ---- main: chunked GEMMs gated per-chunk ----
    cudaStreamWaitEvent(0, evRoute, 0);
    for (int c = 0; c < NCHUNK; c++) {
        cudaStreamWaitEvent(0, evW13c[c], 0);
        w13_k<<<dim3(INTER / 64, MAXMT, ECHUNK), 256, SM_TOT>>>(c * ECHUNK);
    }
    for (int c = 0; c < NCHUNK; c++) {
        cudaStreamWaitEvent(0, evW2c[c], 0);
        w2_k<<<dim3(HID / 128, MAXMT, ECHUNK), 256, SM_TOT>>>(y, c * ECHUNK);
    }
}

// round 15
// speedup vs baseline: 1.1039x; 1.1039x over previous
#include <cuda_runtime.h>
#include <cuda_fp16.h>
#include <math.h>
#include <stdint.h>

#define TOKENS 2048
#define HID    1024
#define NEXP   64
#define INTER  512
#define TOPK   8
#define NGRP   8
#define TOPKG  4

#define ROWB    144
#define STG     18432
#define NSTAGE  3
#define SA_OFF  1024
#define SB_OFF  (SA_OFF + NSTAGE * STG)
#define SM_TOT  (SB_OFF + NSTAGE * STG)   // 111616
#define MAXMT   4
#define KSPLIT  8
#define W13CH   32                        // experts per w13 chunk (2 chunks)

// ---------------- scratch ----------------------------------------------------
__device__ float  g_logits[TOKENS * NEXP];
__device__ int    g_cnt[NEXP];
__device__ int    g_tok[NEXP * TOKENS];
__device__ float  g_wt[NEXP * TOKENS];
__device__ __half g_h[(size_t)NEXP * TOKENS * INTER];
__device__ __half g_w13h[(size_t)NEXP * 2 * INTER * HID];
__device__ __half g_w2h[(size_t)NEXP * HID * INTER];
__device__ __half g_xh[TOKENS * HID];

// ---------------- helpers ----------------------------------------------------
__device__ __forceinline__ uint32_t smem_u32(const void* p) {
    uint32_t a;
    asm("{ .reg .u64 t; cvta.to.shared.u64 t, %1; cvt.u32.u64 %0, t; }" : "=r"(a) : "l"(p));
    return a;
}
__device__ __forceinline__ uint32_t packh2(float a, float b) {
    __half2 h = __float22half2_rn(make_float2(a, b));
    return *(uint32_t*)&h;
}
__device__ __forceinline__ void cpa16(uint32_t dst, const void* src, uint32_t nbytes) {
    asm volatile("cp.async.cg.shared.global [%0], [%1], 16, %2;"
                 :: "r"(dst), "l"(src), "r"(nbytes) : "memory");
}
#define CP_COMMIT() asm volatile("cp.async.commit_group;" ::: "memory")
#define CP_WAIT1()  asm volatile("cp.async.wait_group 1;" ::: "memory")
__device__ __forceinline__ void ldsm_x4(uint32_t r[4], uint32_t addr) {
    asm volatile("ldmatrix.sync.aligned.m8n8.x4.shared.b16 {%0,%1,%2,%3}, [%4];"
                 : "=r"(r[0]), "=r"(r[1]), "=r"(r[2]), "=r"(r[3]) : "r"(addr));
}
__device__ __forceinline__ void mma_f16(float c[4], const uint32_t a[4],
                                        uint32_t b0, uint32_t b1) {
    asm volatile(
        "mma.sync.aligned.m16n8k16.row.col.f32.f16.f16.f32 "
        "{%0,%1,%2,%3},{%4,%5,%6,%7},{%8,%9},{%0,%1,%2,%3};"
        : "+f"(c[0]), "+f"(c[1]), "+f"(c[2]), "+f"(c[3])
        : "r"(a[0]), "r"(a[1]), "r"(a[2]), "r"(a[3]), "r"(b0), "r"(b1));
}
__device__ __forceinline__ float silu(float g) { return g / (1.f + expf(-g)); }
__device__ __forceinline__ void red_add_v2(float* p, float a, float b) {
    asm volatile("red.global.add.v2.f32 [%0], {%1,%2};" :: "l"(p), "f"(a), "f"(b) : "memory");
}
__device__ __forceinline__ void red_add_v4(float* p, float a, float b, float c, float d) {
    asm volatile("red.global.add.v4.f32 [%0], {%1,%2,%3,%4};"
                 :: "l"(p), "f"(a), "f"(b), "f"(c), "f"(d) : "memory");
}

// ---------------- fp32 -> fp16 streaming conversion (MLP=8) ------------------
__global__ __launch_bounds__(256) void conv_kernel(const float4* __restrict__ src,
                                                   uint4* __restrict__ dst, int n4) {
    int base = blockIdx.x * 1024 + threadIdx.x;
    float4 a[8];
#pragma unroll
    for (int p = 0; p < 4; p++) {
        int idx = base + p * 256;
        a[2 * p]     = __ldg(&src[2 * idx]);
        a[2 * p + 1] = __ldg(&src[2 * idx + 1]);
    }
#pragma unroll
    for (int p = 0; p < 4; p++) {
        int idx = base + p * 256;
        uint4 o;
        o.x = packh2(a[2 * p].x,     a[2 * p].y);
        o.y = packh2(a[2 * p].z,     a[2 * p].w);
        o.z = packh2(a[2 * p + 1].x, a[2 * p + 1].y);
        o.w = packh2(a[2 * p + 1].z, a[2 * p + 1].w);
        dst[idx] = o;
    }
}

// ---------------- router: k-split logits GEMM, red.add partials --------------
__global__ __launch_bounds__(256) void router_kernel(const float* __restrict__ x,
                                                     const float* __restrict__ gw) {
    __shared__ float Xs[16][68];
    __shared__ float Gs[16][68];
    const int m0    = blockIdx.x * 64;
    const int kbase = blockIdx.y * (HID / KSPLIT);
    const int tid   = threadIdx.x;
    const int ty    = tid >> 4;
    const int tx    = tid & 15;

    if (blockIdx.x == 0 && blockIdx.y == 0 && tid < NEXP) g_cnt[tid] = 0;

    float acc[4][4];
#pragma unroll
    for (int i = 0; i < 4; i++)
#pragma unroll
        for (int j = 0; j < 4; j++) acc[i][j] = 0.f;

    const int lrow = tid >> 2;
    const int lk   = (tid & 3) * 4;
    const float* xp = x + (size_t)(m0 + lrow) * HID + kbase + lk;
    const float* gp = gw + (size_t)lrow * HID + kbase + lk;

#pragma unroll
    for (int k0 = 0; k0 < HID / KSPLIT; k0 += 16) {
        float4 xv = *(const float4*)(xp + k0);
        float4 gv = *(const float4*)(gp + k0);
        Xs[lk + 0][lrow] = xv.x; Xs[lk + 1][lrow] = xv.y;
        Xs[lk + 2][lrow] = xv.z; Xs[lk + 3][lrow] = xv.w;
        Gs[lk + 0][lrow] = gv.x; Gs[lk + 1][lrow] = gv.y;
        Gs[lk + 2][lrow] = gv.z; Gs[lk + 3][lrow] = gv.w;
        __syncthreads();
#pragma unroll
        for (int k = 0; k < 16; k++) {
            float4 a = *(const float4*)&Xs[k][ty * 4];
            float4 b = *(const float4*)&Gs[k][tx * 4];
            acc[0][0] += a.x * b.x; acc[0][1] += a.x * b.y; acc[0][2] += a.x * b.z; acc[0][3] += a.x * b.w;
            acc[1][0] += a.y * b.x; acc[1][1] += a.y * b.y; acc[1][2] += a.y * b.z; acc[1][3] += a.y * b.w;
            acc[2][0] += a.z * b.x; acc[2][1] += a.z * b.y; acc[2][2] += a.z * b.z; acc[2][3] += a.z * b.w;
            acc[3][0] += a.w * b.x; acc[3][1] += a.w * b.y; acc[3][2] += a.w * b.z; acc[3][3] += a.w * b.w;
        }
        __syncthreads();
    }

#pragma unroll
    for (int i = 0; i < 4; i++) {
        float* dst = g_logits + (size_t)(m0 + ty * 4 + i) * NEXP + tx * 4;
        red_add_v4(dst, acc[i][0], acc[i][1], acc[i][2], acc[i][3]);
    }
}

// ---------------- grouped top-k routing (exact; sigmoid applied here) --------
__global__ void topk_kernel(const float* __restrict__ bias) {
    int t = blockIdx.x * blockDim.x + threadIdx.x;
    if (t >= TOKENS) return;

    float sraw[NEXP], sb[NEXP];
    const float* lg = g_logits + (size_t)t * NEXP;
#pragma unroll
    for (int e = 0; e < NEXP; e++) {
        sraw[e] = 1.f / (1.f + expf(-lg[e]));
        sb[e]   = sraw[e] + bias[e];
    }

    float gs[NGRP];
#pragma unroll
    for (int g = 0; g < NGRP; g++) {
        float m1 = -1e30f, m2 = -1e30f;
#pragma unroll
        for (int j = 0; j < NEXP / NGRP; j++) {
            float v = sb[g * (NEXP / NGRP) + j];
            if (v > m1) { m2 = m1; m1 = v; } else if (v > m2) { m2 = v; }
        }
        gs[g] = m1 + m2;
    }

    unsigned gsel = 0;
    for (int it = 0; it < TOPKG; it++) {
        int best = -1; float bv = -1e30f;
#pragma unroll
        for (int g = 0; g < NGRP; g++)
            if (!((gsel >> g) & 1u) && gs[g] > bv) { bv = gs[g]; best = g; }
        gsel |= 1u << best;
    }

    unsigned long long esel = 0ull;
    int   ids[TOPK];
    float w[TOPK];
    float wsum = 0.f;
    for (int it = 0; it < TOPK; it++) {
        int best = -1; float bv = -1e30f;
#pragma unroll
        for (int e = 0; e < NEXP; e++) {
            if (((gsel >> (e >> 3)) & 1u) && !((esel >> e) & 1ull)) {
                float v = sb[e];
                if (v > bv) { bv = v; best = e; }
            }
        }
        esel |= 1ull << best;
        ids[it] = best;
        w[it]   = sraw[best];
        wsum   += sraw[best];
    }
    float inv = 1.f / wsum;

    for (int it = 0; it < TOPK; it++) {
        int e   = ids[it];
        int pos = atomicAdd(&g_cnt[e], 1);
        g_tok[e * TOKENS + pos] = t;
        g_wt[e * TOKENS + pos]  = w[it] * inv;
    }
}

// ---------------- expert GEMM1 (fp16, BK=64, 3-stage, frag-pipelined) --------
__global__ __launch_bounds__(256, 2) void w13_k(int e0) {
    extern __shared__ char smem[];
    int* stok = (int*)smem;

    const int e   = e0 + blockIdx.z;
    const int cnt = g_cnt[e];
    const int m0  = blockIdx.y * 128;
    if (m0 >= cnt) return;
    const int n0  = blockIdx.x * 64;

    const int tid = threadIdx.x, lane = tid & 31, wid = tid >> 5;
    const int wm = wid & 1, wn = wid >> 1, t4 = lane & 3, g8 = lane >> 2;

    if (tid < 128) stok[tid] = (m0 + tid < cnt) ? g_tok[e * TOKENS + m0 + tid] : -1;
    __syncthreads();

    const uint32_t sbase = smem_u32(smem);

    const __half* asrc[4]; uint32_t asz[4], aoff[4];
    const __half* bsrc[4];
    const __half* w13e = g_w13h + (size_t)e * (2 * INTER) * HID;
#pragma unroll
    for (int p = 0; p < 4; p++) {
        int q   = tid + p * 256;
        int row = q >> 3, c = q & 7;
        int tk  = stok[row];
        asrc[p] = g_xh + (size_t)(tk >= 0 ? tk : 0) * HID + c * 8;
        asz[p]  = (tk >= 0) ? 16u : 0u;
        aoff[p] = row * ROWB + c * 16;
        int bw  = (row < 64) ? (n0 + row) : (INTER + n0 + (row - 64));
        bsrc[p] = w13e + (size_t)bw * HID + c * 8;
    }
    auto load_stage = [&](int s, int k0) {
#pragma unroll
        for (int p = 0; p < 4; p++) {
            cpa16(sbase + SA_OFF + s * STG + aoff[p], asrc[p] + k0, asz[p]);
            cpa16(sbase + SB_OFF + s * STG + aoff[p], bsrc[p] + k0, 16u);
        }
    };

    const int lr  = ((lane >> 3) & 1) * 8 + (lane & 7);
    const int lkb = (lane >> 4) * 16;
    const uint32_t aAddr = sbase + SA_OFF + (wm * 64 + lr) * ROWB + lkb;
    const uint32_t bAddr = sbase + SB_OFF + (wn * 16 + lr) * ROWB + lkb;

    float acc[4][4][4];
#pragma unroll
    for (int i = 0; i < 4; i++)
#pragma unroll
        for (int j = 0; j < 4; j++)
#pragma unroll
            for (int c = 0; c < 4; c++) acc[i][j][c] = 0.f;

    load_stage(0, 0);  CP_COMMIT();
    load_stage(1, 64); CP_COMMIT();

    uint32_t a[2][4][4], bg[2][4], bu[2][4];

    const int NIT = HID / 64;
    int s = 0, sl = 2;
    for (int it = 0; it < NIT; it++) {
        CP_WAIT1();
        __syncthreads();
        if (it + 2 < NIT) load_stage(sl, (it + 2) * 64);
        CP_COMMIT();

        const uint32_t sOff = s * STG;
#pragma unroll
        for (int mf = 0; mf < 4; mf++)
            ldsm_x4(a[0][mf], aAddr + sOff + mf * 16 * ROWB);
        ldsm_x4(bg[0], bAddr + sOff);
        ldsm_x4(bu[0], bAddr + sOff + 64 * ROWB);

#pragma unroll
        for (int ks = 0; ks < 4; ks++) {
            const int cur = ks & 1, nxt = cur ^ 1;
            if (ks < 3) {
#pragma unroll
                for (int mf = 0; mf < 4; mf++)
                    ldsm_x4(a[nxt][mf], aAddr + sOff + mf * 16 * ROWB + (ks + 1) * 32);
                ldsm_x4(bg[nxt], bAddr + sOff + (ks + 1) * 32);
                ldsm_x4(bu[nxt], bAddr + sOff + 64 * ROWB + (ks + 1) * 32);
            }
#pragma unroll
            for (int mf = 0; mf < 4; mf++) {
                mma_f16(acc[mf][0], a[cur][mf], bg[cur][0], bg[cur][2]);
                mma_f16(acc[mf][1], a[cur][mf], bg[cur][1], bg[cur][3]);
                mma_f16(acc[mf][2], a[cur][mf], bu[cur][0], bu[cur][2]);
                mma_f16(acc[mf][3], a[cur][mf], bu[cur][1], bu[cur][3]);
            }
        }
        if (++s == NSTAGE) s = 0;
        if (++sl == NSTAGE) sl = 0;
    }

#pragma unroll
    for (int mf = 0; mf < 4; mf++) {
        int r0 = wm * 64 + mf * 16 + g8;
        int r1 = r0 + 8;
#pragma unroll
        for (int nf = 0; nf < 2; nf++) {
            int c = n0 + wn * 16 + nf * 8 + t4 * 2;
            if (m0 + r0 < cnt) {
                uint32_t o = packh2(silu(acc[mf][nf][0]) * acc[mf][nf + 2][0],
                                    silu(acc[mf][nf][1]) * acc[mf][nf + 2][1]);
                *(uint32_t*)&g_h[((size_t)e * TOKENS + m0 + r0) * INTER + c] = o;
            }
            if (m0 + r1 < cnt) {
                uint32_t o = packh2(silu(acc[mf][nf][2]) * acc[mf][nf + 2][2],
                                    silu(acc[mf][nf][3]) * acc[mf][nf + 2][3]);
                *(uint32_t*)&g_h[((size_t)e * TOKENS + m0 + r1) * INTER + c] = o;
            }
        }
    }
}

// ---------------- expert GEMM2 (fp16, BK=64, 3-stage, frag-pipelined) --------
__global__ __launch_bounds__(256, 2) void w2_k(float* __restrict__ y, int e0) {
    extern __shared__ char smem[];
    int*   stok = (int*)smem;
    float* swt  = (float*)(smem + 512);

    const int e   = e0 + blockIdx.z;
    const int cnt = g_cnt[e];
    const int m0  = blockIdx.y * 128;
    if (m0 >= cnt) return;
    const int n0  = blockIdx.x * 128;

    const int tid = threadIdx.x, lane = tid & 31, wid = tid >> 5;
    const int wm = wid & 1, wn = wid >> 1, t4 = lane & 3, g8 = lane >> 2;

    if (tid < 128) {
        bool v = m0 + tid < cnt;
        stok[tid] = v ? g_tok[e * TOKENS + m0 + tid] : 0;
        swt[tid]  = v ? g_wt[e * TOKENS + m0 + tid] : 0.f;
    }
    __syncthreads();

    const uint32_t sbase = smem_u32(smem);

    const __half* asrc[4]; uint32_t asz[4], aoff[4];
    const __half* bsrc[4];
    const __half* w2e = g_w2h + (size_t)e * HID * INTER;
#pragma unroll
    for (int p = 0; p < 4; p++) {
        int q   = tid + p * 256;
        int row = q >> 3, c = q & 7;
        bool v  = (m0 + row) < cnt;
        asrc[p] = g_h + ((size_t)e * TOKENS + m0 + row) * INTER + c * 8;
        asz[p]  = v ? 16u : 0u;
        aoff[p] = row * ROWB + c * 16;
        bsrc[p] = w2e + (size_t)(n0 + row) * INTER + c * 8;
    }
    auto load_stage = [&](int s, int k0) {
#pragma unroll
        for (int p = 0; p < 4; p++) {
            cpa16(sbase + SA_OFF + s * STG + aoff[p], asrc[p] + k0, asz[p]);
            cpa16(sbase + SB_OFF + s * STG + aoff[p], bsrc[p] + k0, 16u);
        }
    };

    const int lr  = ((lane >> 3) & 1) * 8 + (lane & 7);
    const int lkb = (lane >> 4) * 16;
    const uint32_t aAddr = sbase + SA_OFF + (wm * 64 + lr) * ROWB + lkb;
    const uint32_t bAddr = sbase + SB_OFF + (wn * 32 + lr) * ROWB + lkb;

    float acc[4][4][4];
#pragma unroll
    for (int i = 0; i < 4; i++)
#pragma unroll
        for (int j = 0; j < 4; j++)
#pragma unroll
            for (int c = 0; c < 4; c++) acc[i][j][c] = 0.f;

    load_stage(0, 0);  CP_COMMIT();
    load_stage(1, 64); CP_COMMIT();

    uint32_t a[2][4][4], b0[2][4], b1[2][4];

    const int NIT = INTER / 64;
    int s = 0, sl = 2;
    for (int it = 0; it < NIT; it++) {
        CP_WAIT1();
        __syncthreads();
        if (it + 2 < NIT) load_stage(sl, (it + 2) * 64);
        CP_COMMIT();

        const uint32_t sOff = s * STG;
#pragma unroll
        for (int mf = 0; mf < 4; mf++)
            ldsm_x4(a[0][mf], aAddr + sOff + mf * 16 * ROWB);
        ldsm_x4(b0[0], bAddr + sOff);
        ldsm_x4(b1[0], bAddr + sOff + 16 * ROWB);

#pragma unroll
        for (int ks = 0; ks < 4; ks++) {
            const int cur = ks & 1, nxt = cur ^ 1;
            if (ks < 3) {
#pragma unroll
                for (int mf = 0; mf < 4; mf++)
                    ldsm_x4(a[nxt][mf], aAddr + sOff + mf * 16 * ROWB + (ks + 1) * 32);
                ldsm_x4(b0[nxt], bAddr + sOff + (ks + 1) * 32);
                ldsm_x4(b1[nxt], bAddr + sOff + 16 * ROWB + (ks + 1) * 32);
            }
#pragma unroll
            for (int mf = 0; mf < 4; mf++) {
                mma_f16(acc[mf][0], a[cur][mf], b0[cur][0], b0[cur][2]);
                mma_f16(acc[mf][1], a[cur][mf], b0[cur][1], b0[cur][3]);
                mma_f16(acc[mf][2], a[cur][mf], b1[cur][0], b1[cur][2]);
                mma_f16(acc[mf][3], a[cur][mf], b1[cur][1], b1[cur][3]);
            }
        }
        if (++s == NSTAGE) s = 0;
        if (++sl == NSTAGE) sl = 0;
    }

#pragma unroll
    for (int mf = 0; mf < 4; mf++) {
        int r0 = wm * 64 + mf * 16 + g8;
        int r1 = r0 + 8;
        bool v0 = (m0 + r0) < cnt;
        bool v1 = (m0 + r1) < cnt;
        int   tok0 = stok[r0], tok1 = stok[r1];
        float wt0 = swt[r0],  wt1 = swt[r1];
#pragma unroll
        for (int nf = 0; nf < 4; nf++) {
            int c = n0 + wn * 32 + nf * 8 + t4 * 2;
            if (v0) red_add_v2(&y[(size_t)tok0 * HID + c],
                               wt0 * acc[mf][nf][0], wt0 * acc[mf][nf][1]);
            if (v1) red_add_v2(&y[(size_t)tok1 * HID + c],
                               wt1 * acc[mf][nf][2], wt1 * acc[mf][nf][3]);
        }
    }
}

// ---------------- launch ------------------------------------------------------
extern "C" void kernel_launch(void* const* d_in, const int* in_sizes, int n_in,
                              void* d_out, int out_size) {
    const float* x    = (const float*)d_in[0];
    const float* gw   = (const float*)d_in[1];
    const float* bias = (const float*)d_in[2];
    const float* w13  = (const float*)d_in[3];
    const float* w2   = (const float*)d_in[4];
    float* y = (float*)d_out;

    cudaFuncSetAttribute(w13_k, cudaFuncAttributeMaxDynamicSharedMemorySize, SM_TOT);
    cudaFuncSetAttribute(w2_k,  cudaFuncAttributeMaxDynamicSharedMemorySize, SM_TOT);

    __half *d_w13h, *d_w2h, *d_xh;
    float  *d_logits;
    cudaGetSymbolAddress((void**)&d_w13h,  g_w13h);
    cudaGetSymbolAddress((void**)&d_w2h,   g_w2h);
    cudaGetSymbolAddress((void**)&d_xh,    g_xh);
    cudaGetSymbolAddress((void**)&d_logits, g_logits);

    // streams + events (created once; capture-safe fork/join pattern)
    static cudaStream_t sc = nullptr, sr = nullptr, s4 = nullptr;
    static cudaEvent_t evRoot = nullptr, evRoute = nullptr;
    static cudaEvent_t evC0 = nullptr, evC1 = nullptr, evW2cv = nullptr, evW13b = nullptr;
    if (!sc) {
        cudaStreamCreateWithFlags(&sc, cudaStreamNonBlocking);
        cudaStreamCreateWithFlags(&sr, cudaStreamNonBlocking);
        cudaStreamCreateWithFlags(&s4, cudaStreamNonBlocking);
        cudaEventCreateWithFlags(&evRoot,  cudaEventDisableTiming);
        cudaEventCreateWithFlags(&evRoute, cudaEventDisableTiming);
        cudaEventCreateWithFlags(&evC0,    cudaEventDisableTiming);
        cudaEventCreateWithFlags(&evC1,    cudaEventDisableTiming);
        cudaEventCreateWithFlags(&evW2cv,  cudaEventDisableTiming);
        cudaEventCreateWithFlags(&evW13b,  cudaEventDisableTiming);
    }

    cudaEventRecord(evRoot, 0);

    // ---- sr: logits memset + router + topk (gates all w13 chunks) ----
    cudaStreamWaitEvent(sr, evRoot, 0);
    cudaMemsetAsync(d_logits, 0, (size_t)TOKENS * NEXP * sizeof(float), sr);
    router_kernel<<<dim3(TOKENS / 64, KSPLIT), 256, 0, sr>>>(x, gw);
    topk_kernel<<<TOKENS / 64, 64, 0, sr>>>(bias);
    cudaEventRecord(evRoute, sr);

    // ---- sc: conv_x, w13 conv in 2 chunks, then conv_w2 + y memset ----
    cudaStreamWaitEvent(sc, evRoot, 0);
    {
        int n4 = TOKENS * HID / 8;
        conv_kernel<<<n4 / 1024, 256, 0, sc>>>((const float4*)x, (uint4*)d_xh, n4);

        const size_t w13ChunkElems = (size_t)W13CH * 2 * INTER * HID;
        int n4c = (int)(w13ChunkElems / 8);
        conv_kernel<<<n4c / 1024, 256, 0, sc>>>((const float4*)w13, (uint4*)d_w13h, n4c);
        cudaEventRecord(evC0, sc);
        conv_kernel<<<n4c / 1024, 256, 0, sc>>>((const float4*)(w13 + w13ChunkElems),
                                                (uint4*)(d_w13h + w13ChunkElems), n4c);
        cudaEventRecord(evC1, sc);

        n4 = NEXP * HID * INTER / 8;
        conv_kernel<<<n4 / 1024, 256, 0, sc>>>((const float4*)w2, (uint4*)d_w2h, n4);
        cudaMemsetAsync(y, 0, (size_t)TOKENS * HID * sizeof(float), sc);
        cudaEventRecord(evW2cv, sc);
    }

    // ---- main: w13 chunk 0; s4: w13 chunk 1 (overlapping tails) ----
    cudaStreamWaitEvent(0, evRoute, 0);
    cudaStreamWaitEvent(0, evC0, 0);
    w13_k<<<dim3(INTER / 64, MAXMT, W13CH), 256, SM_TOT>>>(0);

    cudaStreamWaitEvent(s4, evRoute, 0);
    cudaStreamWaitEvent(s4, evC1, 0);
    w13_k<<<dim3(INTER / 64, MAXMT, W13CH), 256, SM_TOT, s4>>>(W13CH);
    cudaEventRecord(evW13b, s4);

    // ---- main: w2 after both w13 halves + conv_w2 + y memset ----
    cudaStreamWaitEvent(0, evW13b, 0);
    cudaStreamWaitEvent(0, evW2cv, 0);
    w2_k<<<dim3(HID / 128, MAXMT, NEXP), 256, SM_TOT>>>(y, 0);
}

// round 16
// speedup vs baseline: 1.1382x; 1.0310x over previous
#include <cuda_runtime.h>
#include <cuda_fp16.h>
#include <math.h>
#include <stdint.h>

#define TOKENS 2048
#define HID    1024
#define NEXP   64
#define INTER  512
#define TOPK   8
#define NGRP   8
#define TOPKG  4

#define ROWB    144
#define STG     18432
#define NSTAGE  3
#define SA_OFF  1024
#define SB_OFF  (SA_OFF + NSTAGE * STG)
#define SM_TOT  (SB_OFF + NSTAGE * STG)   // 111616
#define MAXMT   4
#define KSPLIT  8
#define EHALF   32                        // experts per half

// ---------------- scratch ----------------------------------------------------
__device__ float  g_logits[TOKENS * NEXP];
__device__ int    g_cnt[NEXP];
__device__ int    g_tok[NEXP * TOKENS];
__device__ float  g_wt[NEXP * TOKENS];
__device__ __half g_h[(size_t)NEXP * TOKENS * INTER];
__device__ __half g_w13h[(size_t)NEXP * 2 * INTER * HID];
__device__ __half g_w2h[(size_t)NEXP * HID * INTER];
__device__ __half g_xh[TOKENS * HID];

// ---------------- helpers ----------------------------------------------------
__device__ __forceinline__ uint32_t smem_u32(const void* p) {
    uint32_t a;
    asm("{ .reg .u64 t; cvta.to.shared.u64 t, %1; cvt.u32.u64 %0, t; }" : "=r"(a) : "l"(p));
    return a;
}
__device__ __forceinline__ uint32_t packh2(float a, float b) {
    __half2 h = __float22half2_rn(make_float2(a, b));
    return *(uint32_t*)&h;
}
__device__ __forceinline__ void cpa16(uint32_t dst, const void* src, uint32_t nbytes) {
    asm volatile("cp.async.cg.shared.global [%0], [%1], 16, %2;"
                 :: "r"(dst), "l"(src), "r"(nbytes) : "memory");
}
#define CP_COMMIT() asm volatile("cp.async.commit_group;" ::: "memory")
#define CP_WAIT1()  asm volatile("cp.async.wait_group 1;" ::: "memory")
__device__ __forceinline__ void ldsm_x4(uint32_t r[4], uint32_t addr) {
    asm volatile("ldmatrix.sync.aligned.m8n8.x4.shared.b16 {%0,%1,%2,%3}, [%4];"
                 : "=r"(r[0]), "=r"(r[1]), "=r"(r[2]), "=r"(r[3]) : "r"(addr));
}
__device__ __forceinline__ void mma_f16(float c[4], const uint32_t a[4],
                                        uint32_t b0, uint32_t b1) {
    asm volatile(
        "mma.sync.aligned.m16n8k16.row.col.f32.f16.f16.f32 "
        "{%0,%1,%2,%3},{%4,%5,%6,%7},{%8,%9},{%0,%1,%2,%3};"
        : "+f"(c[0]), "+f"(c[1]), "+f"(c[2]), "+f"(c[3])
        : "r"(a[0]), "r"(a[1]), "r"(a[2]), "r"(a[3]), "r"(b0), "r"(b1));
}
__device__ __forceinline__ float silu(float g) { return g / (1.f + expf(-g)); }
__device__ __forceinline__ void red_add_v2(float* p, float a, float b) {
    asm volatile("red.global.add.v2.f32 [%0], {%1,%2};" :: "l"(p), "f"(a), "f"(b) : "memory");
}
__device__ __forceinline__ void red_add_v4(float* p, float a, float b, float c, float d) {
    asm volatile("red.global.add.v4.f32 [%0], {%1,%2,%3,%4};"
                 :: "l"(p), "f"(a), "f"(b), "f"(c), "f"(d) : "memory");
}

// ---------------- fp32 -> fp16 streaming conversion (MLP=8) ------------------
__global__ __launch_bounds__(256) void conv_kernel(const float4* __restrict__ src,
                                                   uint4* __restrict__ dst, int n4) {
    int base = blockIdx.x * 1024 + threadIdx.x;
    float4 a[8];
#pragma unroll
    for (int p = 0; p < 4; p++) {
        int idx = base + p * 256;
        a[2 * p]     = __ldg(&src[2 * idx]);
        a[2 * p + 1] = __ldg(&src[2 * idx + 1]);
    }
#pragma unroll
    for (int p = 0; p < 4; p++) {
        int idx = base + p * 256;
        uint4 o;
        o.x = packh2(a[2 * p].x,     a[2 * p].y);
        o.y = packh2(a[2 * p].z,     a[2 * p].w);
        o.z = packh2(a[2 * p + 1].x, a[2 * p + 1].y);
        o.w = packh2(a[2 * p + 1].z, a[2 * p + 1].w);
        dst[idx] = o;
    }
}

// ---------------- router: k-split logits GEMM, red.add partials --------------
__global__ __launch_bounds__(256) void router_kernel(const float* __restrict__ x,
                                                     const float* __restrict__ gw) {
    __shared__ float Xs[16][68];
    __shared__ float Gs[16][68];
    const int m0    = blockIdx.x * 64;
    const int kbase = blockIdx.y * (HID / KSPLIT);
    const int tid   = threadIdx.x;
    const int ty    = tid >> 4;
    const int tx    = tid & 15;

    if (blockIdx.x == 0 && blockIdx.y == 0 && tid < NEXP) g_cnt[tid] = 0;

    float acc[4][4];
#pragma unroll
    for (int i = 0; i < 4; i++)
#pragma unroll
        for (int j = 0; j < 4; j++) acc[i][j] = 0.f;

    const int lrow = tid >> 2;
    const int lk   = (tid & 3) * 4;
    const float* xp = x + (size_t)(m0 + lrow) * HID + kbase + lk;
    const float* gp = gw + (size_t)lrow * HID + kbase + lk;

#pragma unroll
    for (int k0 = 0; k0 < HID / KSPLIT; k0 += 16) {
        float4 xv = *(const float4*)(xp + k0);
        float4 gv = *(const float4*)(gp + k0);
        Xs[lk + 0][lrow] = xv.x; Xs[lk + 1][lrow] = xv.y;
        Xs[lk + 2][lrow] = xv.z; Xs[lk + 3][lrow] = xv.w;
        Gs[lk + 0][lrow] = gv.x; Gs[lk + 1][lrow] = gv.y;
        Gs[lk + 2][lrow] = gv.z; Gs[lk + 3][lrow] = gv.w;
        __syncthreads();
#pragma unroll
        for (int k = 0; k < 16; k++) {
            float4 a = *(const float4*)&Xs[k][ty * 4];
            float4 b = *(const float4*)&Gs[k][tx * 4];
            acc[0][0] += a.x * b.x; acc[0][1] += a.x * b.y; acc[0][2] += a.x * b.z; acc[0][3] += a.x * b.w;
            acc[1][0] += a.y * b.x; acc[1][1] += a.y * b.y; acc[1][2] += a.y * b.z; acc[1][3] += a.y * b.w;
            acc[2][0] += a.z * b.x; acc[2][1] += a.z * b.y; acc[2][2] += a.z * b.z; acc[2][3] += a.z * b.w;
            acc[3][0] += a.w * b.x; acc[3][1] += a.w * b.y; acc[3][2] += a.w * b.z; acc[3][3] += a.w * b.w;
        }
        __syncthreads();
    }

#pragma unroll
    for (int i = 0; i < 4; i++) {
        float* dst = g_logits + (size_t)(m0 + ty * 4 + i) * NEXP + tx * 4;
        red_add_v4(dst, acc[i][0], acc[i][1], acc[i][2], acc[i][3]);
    }
}

// ---------------- grouped top-k routing (exact; sigmoid applied here) --------
__global__ void topk_kernel(const float* __restrict__ bias) {
    int t = blockIdx.x * blockDim.x + threadIdx.x;
    if (t >= TOKENS) return;

    float sraw[NEXP], sb[NEXP];
    const float* lg = g_logits + (size_t)t * NEXP;
#pragma unroll
    for (int e = 0; e < NEXP; e++) {
        sraw[e] = 1.f / (1.f + expf(-lg[e]));
        sb[e]   = sraw[e] + bias[e];
    }

    float gs[NGRP];
#pragma unroll
    for (int g = 0; g < NGRP; g++) {
        float m1 = -1e30f, m2 = -1e30f;
#pragma unroll
        for (int j = 0; j < NEXP / NGRP; j++) {
            float v = sb[g * (NEXP / NGRP) + j];
            if (v > m1) { m2 = m1; m1 = v; } else if (v > m2) { m2 = v; }
        }
        gs[g] = m1 + m2;
    }

    unsigned gsel = 0;
    for (int it = 0; it < TOPKG; it++) {
        int best = -1; float bv = -1e30f;
#pragma unroll
        for (int g = 0; g < NGRP; g++)
            if (!((gsel >> g) & 1u) && gs[g] > bv) { bv = gs[g]; best = g; }
        gsel |= 1u << best;
    }

    unsigned long long esel = 0ull;
    int   ids[TOPK];
    float w[TOPK];
    float wsum = 0.f;
    for (int it = 0; it < TOPK; it++) {
        int best = -1; float bv = -1e30f;
#pragma unroll
        for (int e = 0; e < NEXP; e++) {
            if (((gsel >> (e >> 3)) & 1u) && !((esel >> e) & 1ull)) {
                float v = sb[e];
                if (v > bv) { bv = v; best = e; }
            }
        }
        esel |= 1ull << best;
        ids[it] = best;
        w[it]   = sraw[best];
        wsum   += sraw[best];
    }
    float inv = 1.f / wsum;

    for (int it = 0; it < TOPK; it++) {
        int e   = ids[it];
        int pos = atomicAdd(&g_cnt[e], 1);
        g_tok[e * TOKENS + pos] = t;
        g_wt[e * TOKENS + pos]  = w[it] * inv;
    }
}

// ---------------- expert GEMM1 (fp16, BK=64, 3-stage, frag-pipelined) --------
__global__ __launch_bounds__(256, 2) void w13_k(int e0) {
    extern __shared__ char smem[];
    int* stok = (int*)smem;

    const int e   = e0 + blockIdx.z;
    const int cnt = g_cnt[e];
    const int m0  = blockIdx.y * 128;
    if (m0 >= cnt) return;
    const int n0  = blockIdx.x * 64;

    const int tid = threadIdx.x, lane = tid & 31, wid = tid >> 5;
    const int wm = wid & 1, wn = wid >> 1, t4 = lane & 3, g8 = lane >> 2;

    if (tid < 128) stok[tid] = (m0 + tid < cnt) ? g_tok[e * TOKENS + m0 + tid] : -1;
    __syncthreads();

    const uint32_t sbase = smem_u32(smem);

    const __half* asrc[4]; uint32_t asz[4], aoff[4];
    const __half* bsrc[4];
    const __half* w13e = g_w13h + (size_t)e * (2 * INTER) * HID;
#pragma unroll
    for (int p = 0; p < 4; p++) {
        int q   = tid + p * 256;
        int row = q >> 3, c = q & 7;
        int tk  = stok[row];
        asrc[p] = g_xh + (size_t)(tk >= 0 ? tk : 0) * HID + c * 8;
        asz[p]  = (tk >= 0) ? 16u : 0u;
        aoff[p] = row * ROWB + c * 16;
        int bw  = (row < 64) ? (n0 + row) : (INTER + n0 + (row - 64));
        bsrc[p] = w13e + (size_t)bw * HID + c * 8;
    }
    auto load_stage = [&](int s, int k0) {
#pragma unroll
        for (int p = 0; p < 4; p++) {
            cpa16(sbase + SA_OFF + s * STG + aoff[p], asrc[p] + k0, asz[p]);
            cpa16(sbase + SB_OFF + s * STG + aoff[p], bsrc[p] + k0, 16u);
        }
    };

    const int lr  = ((lane >> 3) & 1) * 8 + (lane & 7);
    const int lkb = (lane >> 4) * 16;
    const uint32_t aAddr = sbase + SA_OFF + (wm * 64 + lr) * ROWB + lkb;
    const uint32_t bAddr = sbase + SB_OFF + (wn * 16 + lr) * ROWB + lkb;

    float acc[4][4][4];
#pragma unroll
    for (int i = 0; i < 4; i++)
#pragma unroll
        for (int j = 0; j < 4; j++)
#pragma unroll
            for (int c = 0; c < 4; c++) acc[i][j][c] = 0.f;

    load_stage(0, 0);  CP_COMMIT();
    load_stage(1, 64); CP_COMMIT();

    uint32_t a[2][4][4], bg[2][4], bu[2][4];

    const int NIT = HID / 64;
    int s = 0, sl = 2;
    for (int it = 0; it < NIT; it++) {
        CP_WAIT1();
        __syncthreads();
        if (it + 2 < NIT) load_stage(sl, (it + 2) * 64);
        CP_COMMIT();

        const uint32_t sOff = s * STG;
#pragma unroll
        for (int mf = 0; mf < 4; mf++)
            ldsm_x4(a[0][mf], aAddr + sOff + mf * 16 * ROWB);
        ldsm_x4(bg[0], bAddr + sOff);
        ldsm_x4(bu[0], bAddr + sOff + 64 * ROWB);

#pragma unroll
        for (int ks = 0; ks < 4; ks++) {
            const int cur = ks & 1, nxt = cur ^ 1;
            if (ks < 3) {
#pragma unroll
                for (int mf = 0; mf < 4; mf++)
                    ldsm_x4(a[nxt][mf], aAddr + sOff + mf * 16 * ROWB + (ks + 1) * 32);
                ldsm_x4(bg[nxt], bAddr + sOff + (ks + 1) * 32);
                ldsm_x4(bu[nxt], bAddr + sOff + 64 * ROWB + (ks + 1) * 32);
            }
#pragma unroll
            for (int mf = 0; mf < 4; mf++) {
                mma_f16(acc[mf][0], a[cur][mf], bg[cur][0], bg[cur][2]);
                mma_f16(acc[mf][1], a[cur][mf], bg[cur][1], bg[cur][3]);
                mma_f16(acc[mf][2], a[cur][mf], bu[cur][0], bu[cur][2]);
                mma_f16(acc[mf][3], a[cur][mf], bu[cur][1], bu[cur][3]);
            }
        }
        if (++s == NSTAGE) s = 0;
        if (++sl == NSTAGE) sl = 0;
    }

#pragma unroll
    for (int mf = 0; mf < 4; mf++) {
        int r0 = wm * 64 + mf * 16 + g8;
        int r1 = r0 + 8;
#pragma unroll
        for (int nf = 0; nf < 2; nf++) {
            int c = n0 + wn * 16 + nf * 8 + t4 * 2;
            if (m0 + r0 < cnt) {
                uint32_t o = packh2(silu(acc[mf][nf][0]) * acc[mf][nf + 2][0],
                                    silu(acc[mf][nf][1]) * acc[mf][nf + 2][1]);
                *(uint32_t*)&g_h[((size_t)e * TOKENS + m0 + r0) * INTER + c] = o;
            }
            if (m0 + r1 < cnt) {
                uint32_t o = packh2(silu(acc[mf][nf][2]) * acc[mf][nf + 2][2],
                                    silu(acc[mf][nf][3]) * acc[mf][nf + 2][3]);
                *(uint32_t*)&g_h[((size_t)e * TOKENS + m0 + r1) * INTER + c] = o;
            }
        }
    }
}

// ---------------- expert GEMM2 (fp16, BK=64, 3-stage, frag-pipelined) --------
__global__ __launch_bounds__(256, 2) void w2_k(float* __restrict__ y, int e0) {
    extern __shared__ char smem[];
    int*   stok = (int*)smem;
    float* swt  = (float*)(smem + 512);

    const int e   = e0 + blockIdx.z;
    const int cnt = g_cnt[e];
    const int m0  = blockIdx.y * 128;
    if (m0 >= cnt) return;
    const int n0  = blockIdx.x * 128;

    const int tid = threadIdx.x, lane = tid & 31, wid = tid >> 5;
    const int wm = wid & 1, wn = wid >> 1, t4 = lane & 3, g8 = lane >> 2;

    if (tid < 128) {
        bool v = m0 + tid < cnt;
        stok[tid] = v ? g_tok[e * TOKENS + m0 + tid] : 0;
        swt[tid]  = v ? g_wt[e * TOKENS + m0 + tid] : 0.f;
    }
    __syncthreads();

    const uint32_t sbase = smem_u32(smem);

    const __half* asrc[4]; uint32_t asz[4], aoff[4];
    const __half* bsrc[4];
    const __half* w2e = g_w2h + (size_t)e * HID * INTER;
#pragma unroll
    for (int p = 0; p < 4; p++) {
        int q   = tid + p * 256;
        int row = q >> 3, c = q & 7;
        bool v  = (m0 + row) < cnt;
        asrc[p] = g_h + ((size_t)e * TOKENS + m0 + row) * INTER + c * 8;
        asz[p]  = v ? 16u : 0u;
        aoff[p] = row * ROWB + c * 16;
        bsrc[p] = w2e + (size_t)(n0 + row) * INTER + c * 8;
    }
    auto load_stage = [&](int s, int k0) {
#pragma unroll
        for (int p = 0; p < 4; p++) {
            cpa16(sbase + SA_OFF + s * STG + aoff[p], asrc[p] + k0, asz[p]);
            cpa16(sbase + SB_OFF + s * STG + aoff[p], bsrc[p] + k0, 16u);
        }
    };

    const int lr  = ((lane >> 3) & 1) * 8 + (lane & 7);
    const int lkb = (lane >> 4) * 16;
    const uint32_t aAddr = sbase + SA_OFF + (wm * 64 + lr) * ROWB + lkb;
    const uint32_t bAddr = sbase + SB_OFF + (wn * 32 + lr) * ROWB + lkb;

    float acc[4][4][4];
#pragma unroll
    for (int i = 0; i < 4; i++)
#pragma unroll
        for (int j = 0; j < 4; j++)
#pragma unroll
            for (int c = 0; c < 4; c++) acc[i][j][c] = 0.f;

    load_stage(0, 0);  CP_COMMIT();
    load_stage(1, 64); CP_COMMIT();

    uint32_t a[2][4][4], b0[2][4], b1[2][4];

    const int NIT = INTER / 64;
    int s = 0, sl = 2;
    for (int it = 0; it < NIT; it++) {
        CP_WAIT1();
        __syncthreads();
        if (it + 2 < NIT) load_stage(sl, (it + 2) * 64);
        CP_COMMIT();

        const uint32_t sOff = s * STG;
#pragma unroll
        for (int mf = 0; mf < 4; mf++)
            ldsm_x4(a[0][mf], aAddr + sOff + mf * 16 * ROWB);
        ldsm_x4(b0[0], bAddr + sOff);
        ldsm_x4(b1[0], bAddr + sOff + 16 * ROWB);

#pragma unroll
        for (int ks = 0; ks < 4; ks++) {
            const int cur = ks & 1, nxt = cur ^ 1;
            if (ks < 3) {
#pragma unroll
                for (int mf = 0; mf < 4; mf++)
                    ldsm_x4(a[nxt][mf], aAddr + sOff + mf * 16 * ROWB + (ks + 1) * 32);
                ldsm_x4(b0[nxt], bAddr + sOff + (ks + 1) * 32);
                ldsm_x4(b1[nxt], bAddr + sOff + 16 * ROWB + (ks + 1) * 32);
            }
#pragma unroll
            for (int mf = 0; mf < 4; mf++) {
                mma_f16(acc[mf][0], a[cur][mf], b0[cur][0], b0[cur][2]);
                mma_f16(acc[mf][1], a[cur][mf], b0[cur][1], b0[cur][3]);
                mma_f16(acc[mf][2], a[cur][mf], b1[cur][0], b1[cur][2]);
                mma_f16(acc[mf][3], a[cur][mf], b1[cur][1], b1[cur][3]);
            }
        }
        if (++s == NSTAGE) s = 0;
        if (++sl == NSTAGE) sl = 0;
    }

#pragma unroll
    for (int mf = 0; mf < 4; mf++) {
        int r0 = wm * 64 + mf * 16 + g8;
        int r1 = r0 + 8;
        bool v0 = (m0 + r0) < cnt;
        bool v1 = (m0 + r1) < cnt;
        int   tok0 = stok[r0], tok1 = stok[r1];
        float wt0 = swt[r0],  wt1 = swt[r1];
#pragma unroll
        for (int nf = 0; nf < 4; nf++) {
            int c = n0 + wn * 32 + nf * 8 + t4 * 2;
            if (v0) red_add_v2(&y[(size_t)tok0 * HID + c],
                               wt0 * acc[mf][nf][0], wt0 * acc[mf][nf][1]);
            if (v1) red_add_v2(&y[(size_t)tok1 * HID + c],
                               wt1 * acc[mf][nf][2], wt1 * acc[mf][nf][3]);
        }
    }
}

// ---------------- launch ------------------------------------------------------
extern "C" void kernel_launch(void* const* d_in, const int* in_sizes, int n_in,
                              void* d_out, int out_size) {
    const float* x    = (const float*)d_in[0];
    const float* gw   = (const float*)d_in[1];
    const float* bias = (const float*)d_in[2];
    const float* w13  = (const float*)d_in[3];
    const float* w2   = (const float*)d_in[4];
    float* y = (float*)d_out;

    cudaFuncSetAttribute(w13_k, cudaFuncAttributeMaxDynamicSharedMemorySize, SM_TOT);
    cudaFuncSetAttribute(w2_k,  cudaFuncAttributeMaxDynamicSharedMemorySize, SM_TOT);

    __half *d_w13h, *d_w2h, *d_xh;
    float  *d_logits;
    cudaGetSymbolAddress((void**)&d_w13h,  g_w13h);
    cudaGetSymbolAddress((void**)&d_w2h,   g_w2h);
    cudaGetSymbolAddress((void**)&d_xh,    g_xh);
    cudaGetSymbolAddress((void**)&d_logits, g_logits);

    // streams + events (created once; capture-safe fork/join pattern)
    static cudaStream_t sc = nullptr, sr = nullptr, s4 = nullptr;
    static cudaEvent_t evRoot = nullptr, evRoute = nullptr;
    static cudaEvent_t evC0 = nullptr, evC1 = nullptr;
    static cudaEvent_t evW2a = nullptr, evW2b = nullptr, evS4 = nullptr;
    if (!sc) {
        cudaStreamCreateWithFlags(&sc, cudaStreamNonBlocking);
        cudaStreamCreateWithFlags(&sr, cudaStreamNonBlocking);
        cudaStreamCreateWithFlags(&s4, cudaStreamNonBlocking);
        cudaEventCreateWithFlags(&evRoot,  cudaEventDisableTiming);
        cudaEventCreateWithFlags(&evRoute, cudaEventDisableTiming);
        cudaEventCreateWithFlags(&evC0,    cudaEventDisableTiming);
        cudaEventCreateWithFlags(&evC1,    cudaEventDisableTiming);
        cudaEventCreateWithFlags(&evW2a,   cudaEventDisableTiming);
        cudaEventCreateWithFlags(&evW2b,   cudaEventDisableTiming);
        cudaEventCreateWithFlags(&evS4,    cudaEventDisableTiming);
    }

    cudaEventRecord(evRoot, 0);

    // ---- sr: logits memset + router + topk ----
    cudaStreamWaitEvent(sr, evRoot, 0);
    cudaMemsetAsync(d_logits, 0, (size_t)TOKENS * NEXP * sizeof(float), sr);
    router_kernel<<<dim3(TOKENS / 64, KSPLIT), 256, 0, sr>>>(x, gw);
    topk_kernel<<<TOKENS / 64, 64, 0, sr>>>(bias);
    cudaEventRecord(evRoute, sr);

    // ---- sc: conv_x, y memset, w13 conv halves, w2 conv halves ----
    cudaStreamWaitEvent(sc, evRoot, 0);
    {
        int n4 = TOKENS * HID / 8;
        conv_kernel<<<n4 / 1024, 256, 0, sc>>>((const float4*)x, (uint4*)d_xh, n4);
        cudaMemsetAsync(y, 0, (size_t)TOKENS * HID * sizeof(float), sc);

        const size_t w13Half = (size_t)EHALF * 2 * INTER * HID;
        int n4c = (int)(w13Half / 8);
        conv_kernel<<<n4c / 1024, 256, 0, sc>>>((const float4*)w13, (uint4*)d_w13h, n4c);
        cudaEventRecord(evC0, sc);
        conv_kernel<<<n4c / 1024, 256, 0, sc>>>((const float4*)(w13 + w13Half),
                                                (uint4*)(d_w13h + w13Half), n4c);
        cudaEventRecord(evC1, sc);

        const size_t w2Half = (size_t)EHALF * HID * INTER;
        n4c = (int)(w2Half / 8);
        conv_kernel<<<n4c / 1024, 256, 0, sc>>>((const float4*)w2, (uint4*)d_w2h, n4c);
        cudaEventRecord(evW2a, sc);
        conv_kernel<<<n4c / 1024, 256, 0, sc>>>((const float4*)(w2 + w2Half),
                                                (uint4*)(d_w2h + w2Half), n4c);
        cudaEventRecord(evW2b, sc);
    }

    // ---- main: w13 half0 -> w2 half0 (true deps only) ----
    cudaStreamWaitEvent(0, evRoute, 0);
    cudaStreamWaitEvent(0, evC0, 0);
    w13_k<<<dim3(INTER / 64, MAXMT, EHALF), 256, SM_TOT>>>(0);
    cudaStreamWaitEvent(0, evW2a, 0);   // also covers y memset (earlier on sc)
    w2_k<<<dim3(HID / 128, MAXMT, EHALF), 256, SM_TOT>>>(y, 0);

    // ---- s4: w13 half1 -> w2 half1 ----
    cudaStreamWaitEvent(s4, evRoute, 0);
    cudaStreamWaitEvent(s4, evC1, 0);
    w13_k<<<dim3(INTER / 64, MAXMT, EHALF), 256, SM_TOT, s4>>>(EHALF);
    cudaStreamWaitEvent(s4, evW2b, 0);
    w2_k<<<dim3(HID / 128, MAXMT, EHALF), 256, SM_TOT, s4>>>(y, EHALF);
    cudaEventRecord(evS4, s4);

    // join
    cudaStreamWaitEvent(0, evS4, 0);
}

// round 17
// speedup vs baseline: 1.1438x; 1.0050x over previous
#include <cuda_runtime.h>
#include <cuda_fp16.h>
#include <math.h>
#include <stdint.h>

#define TOKENS 2048
#define HID    1024
#define NEXP   64
#define INTER  512
#define TOPK   8
#define NGRP   8
#define TOPKG  4

#define ROWB    144
#define STG     18432
#define NSTAGE  3
#define SA_OFF  1024
#define SB_OFF  (SA_OFF + NSTAGE * STG)
#define SM_TOT  (SB_OFF + NSTAGE * STG)   // 111616
#define MAXMT   4
#define KSPLIT  8
#define EQ      16                        // experts per w13 conv chunk (4 chunks)
#define EHALF   32                        // experts per GEMM half

// ---------------- scratch ----------------------------------------------------
__device__ float  g_logits[TOKENS * NEXP];
__device__ int    g_cnt[NEXP];
__device__ int    g_tok[NEXP * TOKENS];
__device__ float  g_wt[NEXP * TOKENS];
__device__ __half g_h[(size_t)NEXP * TOKENS * INTER];
__device__ __half g_w13h[(size_t)NEXP * 2 * INTER * HID];
__device__ __half g_w2h[(size_t)NEXP * HID * INTER];
__device__ __half g_xh[TOKENS * HID];

// ---------------- helpers ----------------------------------------------------
__device__ __forceinline__ uint32_t smem_u32(const void* p) {
    uint32_t a;
    asm("{ .reg .u64 t; cvta.to.shared.u64 t, %1; cvt.u32.u64 %0, t; }" : "=r"(a) : "l"(p));
    return a;
}
__device__ __forceinline__ uint32_t packh2(float a, float b) {
    __half2 h = __float22half2_rn(make_float2(a, b));
    return *(uint32_t*)&h;
}
__device__ __forceinline__ void cpa16(uint32_t dst, const void* src, uint32_t nbytes) {
    asm volatile("cp.async.cg.shared.global [%0], [%1], 16, %2;"
                 :: "r"(dst), "l"(src), "r"(nbytes) : "memory");
}
#define CP_COMMIT() asm volatile("cp.async.commit_group;" ::: "memory")
#define CP_WAIT1()  asm volatile("cp.async.wait_group 1;" ::: "memory")
__device__ __forceinline__ void ldsm_x4(uint32_t r[4], uint32_t addr) {
    asm volatile("ldmatrix.sync.aligned.m8n8.x4.shared.b16 {%0,%1,%2,%3}, [%4];"
                 : "=r"(r[0]), "=r"(r[1]), "=r"(r[2]), "=r"(r[3]) : "r"(addr));
}
__device__ __forceinline__ void mma_f16(float c[4], const uint32_t a[4],
                                        uint32_t b0, uint32_t b1) {
    asm volatile(
        "mma.sync.aligned.m16n8k16.row.col.f32.f16.f16.f32 "
        "{%0,%1,%2,%3},{%4,%5,%6,%7},{%8,%9},{%0,%1,%2,%3};"
        : "+f"(c[0]), "+f"(c[1]), "+f"(c[2]), "+f"(c[3])
        : "r"(a[0]), "r"(a[1]), "r"(a[2]), "r"(a[3]), "r"(b0), "r"(b1));
}
__device__ __forceinline__ float silu(float g) { return g / (1.f + expf(-g)); }
__device__ __forceinline__ void red_add_v2(float* p, float a, float b) {
    asm volatile("red.global.add.v2.f32 [%0], {%1,%2};" :: "l"(p), "f"(a), "f"(b) : "memory");
}
__device__ __forceinline__ void red_add_v4(float* p, float a, float b, float c, float d) {
    asm volatile("red.global.add.v4.f32 [%0], {%1,%2,%3,%4};"
                 :: "l"(p), "f"(a), "f"(b), "f"(c), "f"(d) : "memory");
}

// ---------------- fp32 -> fp16 streaming conversion (MLP=8) ------------------
__global__ __launch_bounds__(256) void conv_kernel(const float4* __restrict__ src,
                                                   uint4* __restrict__ dst, int n4) {
    int base = blockIdx.x * 1024 + threadIdx.x;
    float4 a[8];
#pragma unroll
    for (int p = 0; p < 4; p++) {
        int idx = base + p * 256;
        a[2 * p]     = __ldg(&src[2 * idx]);
        a[2 * p + 1] = __ldg(&src[2 * idx + 1]);
    }
#pragma unroll
    for (int p = 0; p < 4; p++) {
        int idx = base + p * 256;
        uint4 o;
        o.x = packh2(a[2 * p].x,     a[2 * p].y);
        o.y = packh2(a[2 * p].z,     a[2 * p].w);
        o.z = packh2(a[2 * p + 1].x, a[2 * p + 1].y);
        o.w = packh2(a[2 * p + 1].z, a[2 * p + 1].w);
        dst[idx] = o;
    }
}

// ---------------- router: k-split logits GEMM, red.add partials --------------
__global__ __launch_bounds__(256) void router_kernel(const float* __restrict__ x,
                                                     const float* __restrict__ gw) {
    __shared__ float Xs[16][68];
    __shared__ float Gs[16][68];
    const int m0    = blockIdx.x * 64;
    const int kbase = blockIdx.y * (HID / KSPLIT);
    const int tid   = threadIdx.x;
    const int ty    = tid >> 4;
    const int tx    = tid & 15;

    if (blockIdx.x == 0 && blockIdx.y == 0 && tid < NEXP) g_cnt[tid] = 0;

    float acc[4][4];
#pragma unroll
    for (int i = 0; i < 4; i++)
#pragma unroll
        for (int j = 0; j < 4; j++) acc[i][j] = 0.f;

    const int lrow = tid >> 2;
    const int lk   = (tid & 3) * 4;
    const float* xp = x + (size_t)(m0 + lrow) * HID + kbase + lk;
    const float* gp = gw + (size_t)lrow * HID + kbase + lk;

#pragma unroll
    for (int k0 = 0; k0 < HID / KSPLIT; k0 += 16) {
        float4 xv = *(const float4*)(xp + k0);
        float4 gv = *(const float4*)(gp + k0);
        Xs[lk + 0][lrow] = xv.x; Xs[lk + 1][lrow] = xv.y;
        Xs[lk + 2][lrow] = xv.z; Xs[lk + 3][lrow] = xv.w;
        Gs[lk + 0][lrow] = gv.x; Gs[lk + 1][lrow] = gv.y;
        Gs[lk + 2][lrow] = gv.z; Gs[lk + 3][lrow] = gv.w;
        __syncthreads();
#pragma unroll
        for (int k = 0; k < 16; k++) {
            float4 a = *(const float4*)&Xs[k][ty * 4];
            float4 b = *(const float4*)&Gs[k][tx * 4];
            acc[0][0] += a.x * b.x; acc[0][1] += a.x * b.y; acc[0][2] += a.x * b.z; acc[0][3] += a.x * b.w;
            acc[1][0] += a.y * b.x; acc[1][1] += a.y * b.y; acc[1][2] += a.y * b.z; acc[1][3] += a.y * b.w;
            acc[2][0] += a.z * b.x; acc[2][1] += a.z * b.y; acc[2][2] += a.z * b.z; acc[2][3] += a.z * b.w;
            acc[3][0] += a.w * b.x; acc[3][1] += a.w * b.y; acc[3][2] += a.w * b.z; acc[3][3] += a.w * b.w;
        }
        __syncthreads();
    }

#pragma unroll
    for (int i = 0; i < 4; i++) {
        float* dst = g_logits + (size_t)(m0 + ty * 4 + i) * NEXP + tx * 4;
        red_add_v4(dst, acc[i][0], acc[i][1], acc[i][2], acc[i][3]);
    }
}

// ---------------- grouped top-k routing (exact; sigmoid applied here) --------
__global__ void topk_kernel(const float* __restrict__ bias) {
    int t = blockIdx.x * blockDim.x + threadIdx.x;
    if (t >= TOKENS) return;

    float sraw[NEXP], sb[NEXP];
    const float* lg = g_logits + (size_t)t * NEXP;
#pragma unroll
    for (int e = 0; e < NEXP; e++) {
        sraw[e] = 1.f / (1.f + expf(-lg[e]));
        sb[e]   = sraw[e] + bias[e];
    }

    float gs[NGRP];
#pragma unroll
    for (int g = 0; g < NGRP; g++) {
        float m1 = -1e30f, m2 = -1e30f;
#pragma unroll
        for (int j = 0; j < NEXP / NGRP; j++) {
            float v = sb[g * (NEXP / NGRP) + j];
            if (v > m1) { m2 = m1; m1 = v; } else if (v > m2) { m2 = v; }
        }
        gs[g] = m1 + m2;
    }

    unsigned gsel = 0;
    for (int it = 0; it < TOPKG; it++) {
        int best = -1; float bv = -1e30f;
#pragma unroll
        for (int g = 0; g < NGRP; g++)
            if (!((gsel >> g) & 1u) && gs[g] > bv) { bv = gs[g]; best = g; }
        gsel |= 1u << best;
    }

    unsigned long long esel = 0ull;
    int   ids[TOPK];
    float w[TOPK];
    float wsum = 0.f;
    for (int it = 0; it < TOPK; it++) {
        int best = -1; float bv = -1e30f;
#pragma unroll
        for (int e = 0; e < NEXP; e++) {
            if (((gsel >> (e >> 3)) & 1u) && !((esel >> e) & 1ull)) {
                float v = sb[e];
                if (v > bv) { bv = v; best = e; }
            }
        }
        esel |= 1ull << best;
        ids[it] = best;
        w[it]   = sraw[best];
        wsum   += sraw[best];
    }
    float inv = 1.f / wsum;

    for (int it = 0; it < TOPK; it++) {
        int e   = ids[it];
        int pos = atomicAdd(&g_cnt[e], 1);
        g_tok[e * TOKENS + pos] = t;
        g_wt[e * TOKENS + pos]  = w[it] * inv;
    }
}

// ---------------- expert GEMM1 (fp16, BK=64, 3-stage, frag-pipelined) --------
__global__ __launch_bounds__(256, 2) void w13_k(int e0) {
    extern __shared__ char smem[];
    int* stok = (int*)smem;

    const int e   = e0 + blockIdx.z;
    const int cnt = g_cnt[e];
    const int m0  = blockIdx.y * 128;
    if (m0 >= cnt) return;
    const int n0  = blockIdx.x * 64;

    const int tid = threadIdx.x, lane = tid & 31, wid = tid >> 5;
    const int wm = wid & 1, wn = wid >> 1, t4 = lane & 3, g8 = lane >> 2;

    if (tid < 128) stok[tid] = (m0 + tid < cnt) ? g_tok[e * TOKENS + m0 + tid] : -1;
    __syncthreads();

    const uint32_t sbase = smem_u32(smem);

    const __half* asrc[4]; uint32_t asz[4], aoff[4];
    const __half* bsrc[4];
    const __half* w13e = g_w13h + (size_t)e * (2 * INTER) * HID;
#pragma unroll
    for (int p = 0; p < 4; p++) {
        int q   = tid + p * 256;
        int row = q >> 3, c = q & 7;
        int tk  = stok[row];
        asrc[p] = g_xh + (size_t)(tk >= 0 ? tk : 0) * HID + c * 8;
        asz[p]  = (tk >= 0) ? 16u : 0u;
        aoff[p] = row * ROWB + c * 16;
        int bw  = (row < 64) ? (n0 + row) : (INTER + n0 + (row - 64));
        bsrc[p] = w13e + (size_t)bw * HID + c * 8;
    }
    auto load_stage = [&](int s, int k0) {
#pragma unroll
        for (int p = 0; p < 4; p++) {
            cpa16(sbase + SA_OFF + s * STG + aoff[p], asrc[p] + k0, asz[p]);
            cpa16(sbase + SB_OFF + s * STG + aoff[p], bsrc[p] + k0, 16u);
        }
    };

    const int lr  = ((lane >> 3) & 1) * 8 + (lane & 7);
    const int lkb = (lane >> 4) * 16;
    const uint32_t aAddr = sbase + SA_OFF + (wm * 64 + lr) * ROWB + lkb;
    const uint32_t bAddr = sbase + SB_OFF + (wn * 16 + lr) * ROWB + lkb;

    float acc[4][4][4];
#pragma unroll
    for (int i = 0; i < 4; i++)
#pragma unroll
        for (int j = 0; j < 4; j++)
#pragma unroll
            for (int c = 0; c < 4; c++) acc[i][j][c] = 0.f;

    load_stage(0, 0);  CP_COMMIT();
    load_stage(1, 64); CP_COMMIT();

    uint32_t a[2][4][4], bg[2][4], bu[2][4];

    const int NIT = HID / 64;
    int s = 0, sl = 2;
    for (int it = 0; it < NIT; it++) {
        CP_WAIT1();
        __syncthreads();
        if (it + 2 < NIT) load_stage(sl, (it + 2) * 64);
        CP_COMMIT();

        const uint32_t sOff = s * STG;
#pragma unroll
        for (int mf = 0; mf < 4; mf++)
            ldsm_x4(a[0][mf], aAddr + sOff + mf * 16 * ROWB);
        ldsm_x4(bg[0], bAddr + sOff);
        ldsm_x4(bu[0], bAddr + sOff + 64 * ROWB);

#pragma unroll
        for (int ks = 0; ks < 4; ks++) {
            const int cur = ks & 1, nxt = cur ^ 1;
            if (ks < 3) {
#pragma unroll
                for (int mf = 0; mf < 4; mf++)
                    ldsm_x4(a[nxt][mf], aAddr + sOff + mf * 16 * ROWB + (ks + 1) * 32);
                ldsm_x4(bg[nxt], bAddr + sOff + (ks + 1) * 32);
                ldsm_x4(bu[nxt], bAddr + sOff + 64 * ROWB + (ks + 1) * 32);
            }
#pragma unroll
            for (int mf = 0; mf < 4; mf++) {
                mma_f16(acc[mf][0], a[cur][mf], bg[cur][0], bg[cur][2]);
                mma_f16(acc[mf][1], a[cur][mf], bg[cur][1], bg[cur][3]);
                mma_f16(acc[mf][2], a[cur][mf], bu[cur][0], bu[cur][2]);
                mma_f16(acc[mf][3], a[cur][mf], bu[cur][1], bu[cur][3]);
            }
        }
        if (++s == NSTAGE) s = 0;
        if (++sl == NSTAGE) sl = 0;
    }

#pragma unroll
    for (int mf = 0; mf < 4; mf++) {
        int r0 = wm * 64 + mf * 16 + g8;
        int r1 = r0 + 8;
#pragma unroll
        for (int nf = 0; nf < 2; nf++) {
            int c = n0 + wn * 16 + nf * 8 + t4 * 2;
            if (m0 + r0 < cnt) {
                uint32_t o = packh2(silu(acc[mf][nf][0]) * acc[mf][nf + 2][0],
                                    silu(acc[mf][nf][1]) * acc[mf][nf + 2][1]);
                *(uint32_t*)&g_h[((size_t)e * TOKENS + m0 + r0) * INTER + c] = o;
            }
            if (m0 + r1 < cnt) {
                uint32_t o = packh2(silu(acc[mf][nf][2]) * acc[mf][nf + 2][2],
                                    silu(acc[mf][nf][3]) * acc[mf][nf + 2][3]);
                *(uint32_t*)&g_h[((size_t)e * TOKENS + m0 + r1) * INTER + c] = o;
            }
        }
    }
}

// ---------------- expert GEMM2 (fp16, BK=64, 3-stage, frag-pipelined) --------
__global__ __launch_bounds__(256, 2) void w2_k(float* __restrict__ y, int e0) {
    extern __shared__ char smem[];
    int*   stok = (int*)smem;
    float* swt  = (float*)(smem + 512);

    const int e   = e0 + blockIdx.z;
    const int cnt = g_cnt[e];
    const int m0  = blockIdx.y * 128;
    if (m0 >= cnt) return;
    const int n0  = blockIdx.x * 128;

    const int tid = threadIdx.x, lane = tid & 31, wid = tid >> 5;
    const int wm = wid & 1, wn = wid >> 1, t4 = lane & 3, g8 = lane >> 2;

    if (tid < 128) {
        bool v = m0 + tid < cnt;
        stok[tid] = v ? g_tok[e * TOKENS + m0 + tid] : 0;
        swt[tid]  = v ? g_wt[e * TOKENS + m0 + tid] : 0.f;
    }
    __syncthreads();

    const uint32_t sbase = smem_u32(smem);

    const __half* asrc[4]; uint32_t asz[4], aoff[4];
    const __half* bsrc[4];
    const __half* w2e = g_w2h + (size_t)e * HID * INTER;
#pragma unroll
    for (int p = 0; p < 4; p++) {
        int q   = tid + p * 256;
        int row = q >> 3, c = q & 7;
        bool v  = (m0 + row) < cnt;
        asrc[p] = g_h + ((size_t)e * TOKENS + m0 + row) * INTER + c * 8;
        asz[p]  = v ? 16u : 0u;
        aoff[p] = row * ROWB + c * 16;
        bsrc[p] = w2e + (size_t)(n0 + row) * INTER + c * 8;
    }
    auto load_stage = [&](int s, int k0) {
#pragma unroll
        for (int p = 0; p < 4; p++) {
            cpa16(sbase + SA_OFF + s * STG + aoff[p], asrc[p] + k0, asz[p]);
            cpa16(sbase + SB_OFF + s * STG + aoff[p], bsrc[p] + k0, 16u);
        }
    };

    const int lr  = ((lane >> 3) & 1) * 8 + (lane & 7);
    const int lkb = (lane >> 4) * 16;
    const uint32_t aAddr = sbase + SA_OFF + (wm * 64 + lr) * ROWB + lkb;
    const uint32_t bAddr = sbase + SB_OFF + (wn * 32 + lr) * ROWB + lkb;

    float acc[4][4][4];
#pragma unroll
    for (int i = 0; i < 4; i++)
#pragma unroll
        for (int j = 0; j < 4; j++)
#pragma unroll
            for (int c = 0; c < 4; c++) acc[i][j][c] = 0.f;

    load_stage(0, 0);  CP_COMMIT();
    load_stage(1, 64); CP_COMMIT();

    uint32_t a[2][4][4], b0[2][4], b1[2][4];

    const int NIT = INTER / 64;
    int s = 0, sl = 2;
    for (int it = 0; it < NIT; it++) {
        CP_WAIT1();
        __syncthreads();
        if (it + 2 < NIT) load_stage(sl, (it + 2) * 64);
        CP_COMMIT();

        const uint32_t sOff = s * STG;
#pragma unroll
        for (int mf = 0; mf < 4; mf++)
            ldsm_x4(a[0][mf], aAddr + sOff + mf * 16 * ROWB);
        ldsm_x4(b0[0], bAddr + sOff);
        ldsm_x4(b1[0], bAddr + sOff + 16 * ROWB);

#pragma unroll
        for (int ks = 0; ks < 4; ks++) {
            const int cur = ks & 1, nxt = cur ^ 1;
            if (ks < 3) {
#pragma unroll
                for (int mf = 0; mf < 4; mf++)
                    ldsm_x4(a[nxt][mf], aAddr + sOff + mf * 16 * ROWB + (ks + 1) * 32);
                ldsm_x4(b0[nxt], bAddr + sOff + (ks + 1) * 32);
                ldsm_x4(b1[nxt], bAddr + sOff + 16 * ROWB + (ks + 1) * 32);
            }
#pragma unroll
            for (int mf = 0; mf < 4; mf++) {
                mma_f16(acc[mf][0], a[cur][mf], b0[cur][0], b0[cur][2]);
                mma_f16(acc[mf][1], a[cur][mf], b0[cur][1], b0[cur][3]);
                mma_f16(acc[mf][2], a[cur][mf], b1[cur][0], b1[cur][2]);
                mma_f16(acc[mf][3], a[cur][mf], b1[cur][1], b1[cur][3]);
            }
        }
        if (++s == NSTAGE) s = 0;
        if (++sl == NSTAGE) sl = 0;
    }

#pragma unroll
    for (int mf = 0; mf < 4; mf++) {
        int r0 = wm * 64 + mf * 16 + g8;
        int r1 = r0 + 8;
        bool v0 = (m0 + r0) < cnt;
        bool v1 = (m0 + r1) < cnt;
        int   tok0 = stok[r0], tok1 = stok[r1];
        float wt0 = swt[r0],  wt1 = swt[r1];
#pragma unroll
        for (int nf = 0; nf < 4; nf++) {
            int c = n0 + wn * 32 + nf * 8 + t4 * 2;
            if (v0) red_add_v2(&y[(size_t)tok0 * HID + c],
                               wt0 * acc[mf][nf][0], wt0 * acc[mf][nf][1]);
            if (v1) red_add_v2(&y[(size_t)tok1 * HID + c],
                               wt1 * acc[mf][nf][2], wt1 * acc[mf][nf][3]);
        }
    }
}

// ---------------- launch ------------------------------------------------------
extern "C" void kernel_launch(void* const* d_in, const int* in_sizes, int n_in,
                              void* d_out, int out_size) {
    const float* x    = (const float*)d_in[0];
    const float* gw   = (const float*)d_in[1];
    const float* bias = (const float*)d_in[2];
    const float* w13  = (const float*)d_in[3];
    const float* w2   = (const float*)d_in[4];
    float* y = (float*)d_out;

    cudaFuncSetAttribute(w13_k, cudaFuncAttributeMaxDynamicSharedMemorySize, SM_TOT);
    cudaFuncSetAttribute(w2_k,  cudaFuncAttributeMaxDynamicSharedMemorySize, SM_TOT);

    __half *d_w13h, *d_w2h, *d_xh;
    float  *d_logits;
    cudaGetSymbolAddress((void**)&d_w13h,  g_w13h);
    cudaGetSymbolAddress((void**)&d_w2h,   g_w2h);
    cudaGetSymbolAddress((void**)&d_xh,    g_xh);
    cudaGetSymbolAddress((void**)&d_logits, g_logits);

    // streams + events (created once; capture-safe fork/join pattern)
    static cudaStream_t sc = nullptr, sr = nullptr, s4 = nullptr;
    static cudaEvent_t evRoot = nullptr, evRoute = nullptr, evS4 = nullptr;
    static cudaEvent_t evC[4], evW2a = nullptr, evW2b = nullptr;
    if (!sc) {
        cudaStreamCreateWithFlags(&sc, cudaStreamNonBlocking);
        cudaStreamCreateWithFlags(&sr, cudaStreamNonBlocking);
        cudaStreamCreateWithFlags(&s4, cudaStreamNonBlocking);
        cudaEventCreateWithFlags(&evRoot,  cudaEventDisableTiming);
        cudaEventCreateWithFlags(&evRoute, cudaEventDisableTiming);
        cudaEventCreateWithFlags(&evS4,    cudaEventDisableTiming);
        for (int c = 0; c < 4; c++) cudaEventCreateWithFlags(&evC[c], cudaEventDisableTiming);
        cudaEventCreateWithFlags(&evW2a, cudaEventDisableTiming);
        cudaEventCreateWithFlags(&evW2b, cudaEventDisableTiming);
    }

    cudaEventRecord(evRoot, 0);

    // ---- sr: logits memset + router + topk ----
    cudaStreamWaitEvent(sr, evRoot, 0);
    cudaMemsetAsync(d_logits, 0, (size_t)TOKENS * NEXP * sizeof(float), sr);
    router_kernel<<<dim3(TOKENS / 64, KSPLIT), 256, 0, sr>>>(x, gw);
    topk_kernel<<<TOKENS / 64, 64, 0, sr>>>(bias);
    cudaEventRecord(evRoute, sr);

    // ---- sc: conv_x, y memset, w13 conv in 4 chunks, w2 conv in 2 halves ----
    cudaStreamWaitEvent(sc, evRoot, 0);
    {
        int n4 = TOKENS * HID / 8;
        conv_kernel<<<n4 / 1024, 256, 0, sc>>>((const float4*)x, (uint4*)d_xh, n4);
        cudaMemsetAsync(y, 0, (size_t)TOKENS * HID * sizeof(float), sc);

        const size_t w13Q = (size_t)EQ * 2 * INTER * HID;
        int n4q = (int)(w13Q / 8);
        for (int c = 0; c < 4; c++) {
            conv_kernel<<<n4q / 1024, 256, 0, sc>>>((const float4*)(w13 + c * w13Q),
                                                    (uint4*)(d_w13h + c * w13Q), n4q);
            cudaEventRecord(evC[c], sc);
        }

        const size_t w2Half = (size_t)EHALF * HID * INTER;
        int n4h = (int)(w2Half / 8);
        conv_kernel<<<n4h / 1024, 256, 0, sc>>>((const float4*)w2, (uint4*)d_w2h, n4h);
        cudaEventRecord(evW2a, sc);
        conv_kernel<<<n4h / 1024, 256, 0, sc>>>((const float4*)(w2 + w2Half),
                                                (uint4*)(d_w2h + w2Half), n4h);
        cudaEventRecord(evW2b, sc);
    }

    // ---- main: w13 chunks 0,1 -> w2 half0 (experts 0-31) ----
    cudaStreamWaitEvent(0, evRoute, 0);
    cudaStreamWaitEvent(0, evC[0], 0);
    w13_k<<<dim3(INTER / 64, MAXMT, EQ), 256, SM_TOT>>>(0);
    cudaStreamWaitEvent(0, evC[1], 0);
    w13_k<<<dim3(INTER / 64, MAXMT, EQ), 256, SM_TOT>>>(EQ);
    cudaStreamWaitEvent(0, evW2a, 0);   // y memset ordered earlier on sc
    w2_k<<<dim3(HID / 128, MAXMT, EHALF), 256, SM_TOT>>>(y, 0);

    // ---- s4: w13 chunks 2,3 -> w2 half1 (experts 32-63) ----
    cudaStreamWaitEvent(s4, evRoute, 0);
    cudaStreamWaitEvent(s4, evC[2], 0);
    w13_k<<<dim3(INTER / 64, MAXMT, EQ), 256, SM_TOT, s4>>>(2 * EQ);
    cudaStreamWaitEvent(s4, evC[3], 0);
    w13_k<<<dim3(INTER / 64, MAXMT, EQ), 256, SM_TOT, s4>>>(3 * EQ);
    cudaStreamWaitEvent(s4, evW2b, 0);
    w2_k<<<dim3(HID / 128, MAXMT, EHALF), 256, SM_TOT, s4>>>(y, EHALF);
    cudaEventRecord(evS4, s4);

    // join
    cudaStreamWaitEvent(0, evS4, 0);
}